// round 1
// baseline (speedup 1.0000x reference)
#include <cuda_runtime.h>
#include <math.h>

// Problem constants (shapes are fixed by the dataset)
#define B_SZ   32
#define S_LEN  577
#define E_DIM  768
#define NH     12
#define DH     64
#define BH     (B_SZ * NH)        // 384
#define M_ROWS (B_SZ * S_LEN)     // 18464
#define QKV_F  (3 * E_DIM)        // 2304

// Scratch (device globals: allocation-free per harness rules)
__device__ float g_qkv[(size_t)M_ROWS * QKV_F];          // [B,S,3,H,Dh]  ~170MB
__device__ float g_attn[(size_t)BH * S_LEN * S_LEN];     // [B,H,S,S]     ~511MB
__device__ float g_ctx[(size_t)M_ROWS * E_DIM];          // [B,S,E]       ~57MB

// ---------------------------------------------------------------------------
// Generic C[M,N] = A[M,K] @ B[N,K]^T   (A row-major, B row-major [N,K])
// 128x128 tile, BK=8, 256 threads, 8x8 per thread.
// N must be a multiple of 128 and K a multiple of 8 (true for all our calls).
// ---------------------------------------------------------------------------
__global__ __launch_bounds__(256) void sgemm_nt(const float* __restrict__ A,
                                                const float* __restrict__ B,
                                                float* __restrict__ C,
                                                int M, int N, int K)
{
    __shared__ float As[8][128];
    __shared__ float Bs[8][128];

    const int tid  = threadIdx.x;
    const int tx   = tid & 15;
    const int ty   = tid >> 4;
    const int row0 = blockIdx.y * 128;
    const int col0 = blockIdx.x * 128;
    const int lr   = tid >> 1;         // 0..127
    const int lc   = (tid & 1) * 4;    // 0 or 4

    float acc[8][8];
#pragma unroll
    for (int i = 0; i < 8; i++)
#pragma unroll
        for (int j = 0; j < 8; j++) acc[i][j] = 0.f;

    for (int k0 = 0; k0 < K; k0 += 8) {
        float4 av = make_float4(0.f, 0.f, 0.f, 0.f);
        if (row0 + lr < M)
            av = *reinterpret_cast<const float4*>(&A[(size_t)(row0 + lr) * K + k0 + lc]);
        As[lc + 0][lr] = av.x; As[lc + 1][lr] = av.y;
        As[lc + 2][lr] = av.z; As[lc + 3][lr] = av.w;

        float4 bv = *reinterpret_cast<const float4*>(&B[(size_t)(col0 + lr) * K + k0 + lc]);
        Bs[lc + 0][lr] = bv.x; Bs[lc + 1][lr] = bv.y;
        Bs[lc + 2][lr] = bv.z; Bs[lc + 3][lr] = bv.w;
        __syncthreads();

#pragma unroll
        for (int k = 0; k < 8; k++) {
            float ra[8], rb[8];
#pragma unroll
            for (int i = 0; i < 8; i++) ra[i] = As[k][ty * 8 + i];
#pragma unroll
            for (int j = 0; j < 8; j++) rb[j] = Bs[k][tx * 8 + j];
#pragma unroll
            for (int i = 0; i < 8; i++)
#pragma unroll
                for (int j = 0; j < 8; j++)
                    acc[i][j] = fmaf(ra[i], rb[j], acc[i][j]);
        }
        __syncthreads();
    }

#pragma unroll
    for (int i = 0; i < 8; i++) {
        int m = row0 + ty * 8 + i;
        if (m >= M) continue;
#pragma unroll
        for (int j = 0; j < 8; j += 4) {
            float4 v = make_float4(acc[i][j], acc[i][j + 1], acc[i][j + 2], acc[i][j + 3]);
            *reinterpret_cast<float4*>(&C[(size_t)m * N + col0 + tx * 8 + j]) = v;
        }
    }
}

// ---------------------------------------------------------------------------
// RoPE (roll-by-1 variant, per reference) applied in-place to q,k patch tokens.
// One warp per (b, patch p, t in {q,k}, h). Lane handles d and d+32.
// ---------------------------------------------------------------------------
__global__ __launch_bounds__(256) void rope_kernel()
{
    const int gwarp = (blockIdx.x * blockDim.x + threadIdx.x) >> 5;
    const int lane  = threadIdx.x & 31;

    // gwarp = ((b*576 + p)*2 + t)*12 + h
    int h  = gwarp % 12;
    int w2 = gwarp / 12;
    int t  = w2 & 1;
    int w3 = w2 >> 1;
    int p  = w3 % 576;
    int b  = w3 / 576;
    if (b >= B_SZ) return;

    const int s = p + 1;  // skip CLS token
    float* base = &g_qkv[(((size_t)(b * S_LEN + s) * 3) + t) * E_DIM + h * DH];

    float v0 = base[lane];
    float v1 = base[lane + 32];
    const unsigned full = 0xffffffffu;
    float p0 = __shfl_sync(full, v0, (lane + 31) & 31);
    float p1 = __shfl_sync(full, v1, (lane + 31) & 31);

    // coords: x = col = p%24, y = row = p/24; normalized by (23 + 1e-8)
    float xc = (float)(p % 24) * (1.0f / 23.00000001f);
    float yc = (float)(p / 24) * (1.0f / 23.00000001f);
    int   fi = lane >> 1;  // frequency index, repeated 2x
    // div = exp(-(2*fi) * ln(10000)/32)
    float dv = expf(-(float)(2 * fi) * (9.210340371976184f / 32.0f));
    float ax = xc * dv;
    float ay = yc * dv;

    float rx = v0 * cosf(ax) + p0 * sinf(ax);
    float ry = v1 * cosf(ay) + p1 * sinf(ay);

    base[lane]      = rx;
    base[lane + 32] = ry;
}

// ---------------------------------------------------------------------------
// attn[bh, i, j] = (1/8) * sum_d q[b,h,i,d] * k[b,h,j,d]
// 64x64 output tile per block; K tile stored transposed for conflict-free LDS.
// ---------------------------------------------------------------------------
__global__ __launch_bounds__(256) void attn_scores()
{
    __shared__ float Qs[64][65];    // [row i][d]
    __shared__ float KsT[64][65];   // [d][row j]

    const int bh = blockIdx.z;
    const int b  = bh / NH;
    const int h  = bh % NH;
    const int i0 = blockIdx.y * 64;
    const int j0 = blockIdx.x * 64;
    const int tid = threadIdx.x;

#pragma unroll
    for (int it = 0; it < 16; it++) {
        int idx = tid + it * 256;
        int r = idx >> 6, d = idx & 63;
        int si = i0 + r, sj = j0 + r;
        Qs[r][d]  = (si < S_LEN)
            ? g_qkv[(((size_t)(b * S_LEN + si) * 3) + 0) * E_DIM + h * DH + d] : 0.f;
        KsT[d][r] = (sj < S_LEN)
            ? g_qkv[(((size_t)(b * S_LEN + sj) * 3) + 1) * E_DIM + h * DH + d] : 0.f;
    }
    __syncthreads();

    const int tx = tid & 15, ty = tid >> 4;
    float acc[4][4] = {};
#pragma unroll
    for (int k = 0; k < 64; k++) {
        float qr[4], kr[4];
#pragma unroll
        for (int ii = 0; ii < 4; ii++) qr[ii] = Qs[ty * 4 + ii][k];
#pragma unroll
        for (int jj = 0; jj < 4; jj++) kr[jj] = KsT[k][tx * 4 + jj];
#pragma unroll
        for (int ii = 0; ii < 4; ii++)
#pragma unroll
            for (int jj = 0; jj < 4; jj++)
                acc[ii][jj] = fmaf(qr[ii], kr[jj], acc[ii][jj]);
    }

#pragma unroll
    for (int ii = 0; ii < 4; ii++) {
        int i = i0 + ty * 4 + ii;
        if (i >= S_LEN) continue;
#pragma unroll
        for (int jj = 0; jj < 4; jj++) {
            int j = j0 + tx * 4 + jj;
            if (j < S_LEN)
                g_attn[((size_t)bh * S_LEN + i) * S_LEN + j] = acc[ii][jj] * 0.125f;
        }
    }
}

// ---------------------------------------------------------------------------
// Row softmax over 577 elements; one block per row.
// ---------------------------------------------------------------------------
__global__ __launch_bounds__(256) void softmax_rows()
{
    const size_t row = blockIdx.x;
    float* p = g_attn + row * S_LEN;
    const int tid = threadIdx.x;
    const int wid = tid >> 5, lane = tid & 31;

    __shared__ float red[8];
    __shared__ float bmax, bsum;

    float vals[3];
    float m = -1e30f;
#pragma unroll
    for (int it = 0; it < 3; it++) {
        int j = tid + it * 256;
        vals[it] = (j < S_LEN) ? p[j] : -1e30f;
        m = fmaxf(m, vals[it]);
    }
#pragma unroll
    for (int o = 16; o; o >>= 1) m = fmaxf(m, __shfl_xor_sync(0xffffffffu, m, o));
    if (lane == 0) red[wid] = m;
    __syncthreads();
    if (tid == 0) {
        float t = red[0];
#pragma unroll
        for (int i = 1; i < 8; i++) t = fmaxf(t, red[i]);
        bmax = t;
    }
    __syncthreads();
    m = bmax;

    float e[3];
    float s = 0.f;
#pragma unroll
    for (int it = 0; it < 3; it++) {
        int j = tid + it * 256;
        e[it] = (j < S_LEN) ? __expf(vals[it] - m) : 0.f;
        s += e[it];
    }
#pragma unroll
    for (int o = 16; o; o >>= 1) s += __shfl_xor_sync(0xffffffffu, s, o);
    if (lane == 0) red[wid] = s;
    __syncthreads();
    if (tid == 0) {
        float t = 0.f;
#pragma unroll
        for (int i = 0; i < 8; i++) t += red[i];
        bsum = t;
    }
    __syncthreads();
    float inv = 1.0f / bsum;

#pragma unroll
    for (int it = 0; it < 3; it++) {
        int j = tid + it * 256;
        if (j < S_LEN) p[j] = e[it] * inv;
    }
}

// ---------------------------------------------------------------------------
// ctx[b, i, h*64+d] = sum_j attn[bh,i,j] * v[b,h,j,d]
// 64(i) x 64(d) tile per block, j tiled by 64 (10 iters).
// ---------------------------------------------------------------------------
__global__ __launch_bounds__(256) void attn_ctx()
{
    __shared__ float Ps[64][65];   // [i][j]
    __shared__ float Vs[64][65];   // [j][d]

    const int bh = blockIdx.y;
    const int b  = bh / NH;
    const int h  = bh % NH;
    const int i0 = blockIdx.x * 64;
    const int tid = threadIdx.x;
    const int tx = tid & 15, ty = tid >> 4;

    float acc[4][4] = {};

    for (int j0 = 0; j0 < S_LEN; j0 += 64) {
#pragma unroll
        for (int it = 0; it < 16; it++) {
            int idx = tid + it * 256;
            int r = idx >> 6, c = idx & 63;
            int i = i0 + r, j = j0 + c;
            Ps[r][c] = (i < S_LEN && j < S_LEN)
                ? g_attn[((size_t)bh * S_LEN + i) * S_LEN + j] : 0.f;
            int jv = j0 + r;
            Vs[r][c] = (jv < S_LEN)
                ? g_qkv[(((size_t)(b * S_LEN + jv) * 3) + 2) * E_DIM + h * DH + c] : 0.f;
        }
        __syncthreads();

#pragma unroll
        for (int k = 0; k < 64; k++) {
            float pr[4], vr[4];
#pragma unroll
            for (int ii = 0; ii < 4; ii++) pr[ii] = Ps[ty * 4 + ii][k];
#pragma unroll
            for (int jj = 0; jj < 4; jj++) vr[jj] = Vs[k][tx * 4 + jj];
#pragma unroll
            for (int ii = 0; ii < 4; ii++)
#pragma unroll
                for (int jj = 0; jj < 4; jj++)
                    acc[ii][jj] = fmaf(pr[ii], vr[jj], acc[ii][jj]);
        }
        __syncthreads();
    }

#pragma unroll
    for (int ii = 0; ii < 4; ii++) {
        int i = i0 + ty * 4 + ii;
        if (i >= S_LEN) continue;
#pragma unroll
        for (int jj = 0; jj < 4; jj++) {
            g_ctx[(size_t)(b * S_LEN + i) * E_DIM + h * DH + tx * 4 + jj] = acc[ii][jj];
        }
    }
}

// ---------------------------------------------------------------------------
extern "C" void kernel_launch(void* const* d_in, const int* in_sizes, int n_in,
                              void* d_out, int out_size)
{
    (void)in_sizes; (void)n_in; (void)out_size;
    const float* x      = (const float*)d_in[0];
    const float* w_qkv  = (const float*)d_in[1];
    const float* w_proj = (const float*)d_in[2];
    float* out = (float*)d_out;

    float *qkv_ptr = nullptr, *ctx_ptr = nullptr;
    cudaGetSymbolAddress((void**)&qkv_ptr, g_qkv);
    cudaGetSymbolAddress((void**)&ctx_ptr, g_ctx);

    // 1) QKV projection: [18464,768] @ [2304,768]^T -> [18464,2304]
    {
        dim3 grid(QKV_F / 128, (M_ROWS + 127) / 128);
        sgemm_nt<<<grid, 256>>>(x, w_qkv, qkv_ptr, M_ROWS, QKV_F, E_DIM);
    }

    // 2) RoPE on q,k patch tokens (in place)
    {
        int warps = B_SZ * 576 * 2 * NH;      // 442368
        rope_kernel<<<(warps * 32) / 256, 256>>>();
    }

    // 3) Scores: q @ k^T * 1/8
    {
        dim3 grid((S_LEN + 63) / 64, (S_LEN + 63) / 64, BH);  // (10,10,384)
        attn_scores<<<grid, 256>>>();
    }

    // 4) Softmax over last dim
    softmax_rows<<<BH * S_LEN, 256>>>();

    // 5) ctx = attn @ v, written directly in [B,S,E] layout
    {
        dim3 grid((S_LEN + 63) / 64, BH);     // (10,384)
        attn_ctx<<<grid, 256>>>();
    }

    // 6) Output projection: ctx @ w_proj^T
    {
        dim3 grid(E_DIM / 128, (M_ROWS + 127) / 128);
        sgemm_nt<<<grid, 256>>>(ctx_ptr, w_proj, out, M_ROWS, E_DIM, E_DIM);
    }
}

// round 4
// speedup vs baseline: 1.1197x; 1.1197x over previous
#include <cuda_runtime.h>
#include <math.h>

#define B_SZ   32
#define S_LEN  577
#define E_DIM  768
#define NH     12
#define DH     64
#define M_ROWS (B_SZ * S_LEN)      // 18464
#define QKV_F  (3 * E_DIM)         // 2304
#define HSTRIDE ((size_t)B_SZ * NH * S_LEN * DH)   // per-(q/k/v) stride in g_qkv

// Scratch (device globals; allocation-free per harness rules)
__device__ float g_qkv[(size_t)3 * B_SZ * NH * S_LEN * DH];  // [t][b][h][s][d] ~170MB
__device__ float g_ctx[(size_t)M_ROWS * E_DIM];              // [b][s][h*64+d]  ~57MB

typedef unsigned long long u64;

// ---- packed fp32x2 helpers (exact IEEE fp32, 2x fma-pipe throughput) ----
__device__ __forceinline__ u64 pack2(float lo, float hi) {
    u64 r; asm("mov.b64 %0, {%1, %2};" : "=l"(r) : "f"(lo), "f"(hi)); return r;
}
__device__ __forceinline__ float2 unpk(u64 v) {
    float2 f; asm("mov.b64 {%0, %1}, %2;" : "=f"(f.x), "=f"(f.y) : "l"(v)); return f;
}
__device__ __forceinline__ u64 ffma2(u64 a, u64 b, u64 c) {
    u64 d; asm("fma.rn.f32x2 %0, %1, %2, %3;" : "=l"(d) : "l"(a), "l"(b), "l"(c)); return d;
}
__device__ __forceinline__ u64 fmul2(u64 a, u64 b) {
    u64 d; asm("mul.rn.f32x2 %0, %1, %2;" : "=l"(d) : "l"(a), "l"(b)); return d;
}

// ---------------------------------------------------------------------------
// GEMM: C[M,N] = A[M,K] @ W[N,K]^T, fp32 via f32x2. 128x128 tile, BK=8,
// 256 threads, 8x8 per thread. A is stored DUPLICATED in smem so the
// broadcast operand loads directly as u64 pairs (no pack instructions).
// QKV=true: writes into g_qkv with [t][b][h][s][d] permutation.
// ---------------------------------------------------------------------------
template<bool QKV>
__global__ __launch_bounds__(256) void sgemm_f2(const float* __restrict__ A,
                                                const float* __restrict__ W,
                                                float* __restrict__ C)
{
    const int N = QKV ? QKV_F : E_DIM;
    const int K = E_DIM;
    __shared__ float As2[8][256];   // duplicated A: [k][2*m]
    __shared__ float Bs[8][128];

    const int tid  = threadIdx.x;
    const int tx   = tid & 15;
    const int ty   = tid >> 4;
    const int row0 = blockIdx.y * 128;
    const int col0 = blockIdx.x * 128;
    const int lr   = tid >> 1;
    const int lc   = (tid & 1) * 4;

    u64 acc2[8][4] = {};

    for (int k0 = 0; k0 < K; k0 += 8) {
        float4 av = make_float4(0.f, 0.f, 0.f, 0.f);
        if (row0 + lr < M_ROWS)
            av = *(const float4*)&A[(size_t)(row0 + lr) * K + k0 + lc];
        As2[lc + 0][2*lr] = av.x; As2[lc + 0][2*lr + 1] = av.x;
        As2[lc + 1][2*lr] = av.y; As2[lc + 1][2*lr + 1] = av.y;
        As2[lc + 2][2*lr] = av.z; As2[lc + 2][2*lr + 1] = av.z;
        As2[lc + 3][2*lr] = av.w; As2[lc + 3][2*lr + 1] = av.w;

        float4 bv = *(const float4*)&W[(size_t)(col0 + lr) * K + k0 + lc];
        Bs[lc + 0][lr] = bv.x; Bs[lc + 1][lr] = bv.y;
        Bs[lc + 2][lr] = bv.z; Bs[lc + 3][lr] = bv.w;
        __syncthreads();

#pragma unroll
        for (int k = 0; k < 8; k++) {
            ulonglong2 a01 = *(const ulonglong2*)&As2[k][2*(ty*8) + 0];
            ulonglong2 a23 = *(const ulonglong2*)&As2[k][2*(ty*8) + 4];
            ulonglong2 a45 = *(const ulonglong2*)&As2[k][2*(ty*8) + 8];
            ulonglong2 a67 = *(const ulonglong2*)&As2[k][2*(ty*8) + 12];
            ulonglong2 b01 = *(const ulonglong2*)&Bs[k][tx*8 + 0];
            ulonglong2 b23 = *(const ulonglong2*)&Bs[k][tx*8 + 4];
            u64 ad[8] = {a01.x, a01.y, a23.x, a23.y, a45.x, a45.y, a67.x, a67.y};
            u64 bp[4] = {b01.x, b01.y, b23.x, b23.y};
#pragma unroll
            for (int i = 0; i < 8; i++)
#pragma unroll
                for (int j = 0; j < 4; j++)
                    acc2[i][j] = ffma2(ad[i], bp[j], acc2[i][j]);
        }
        __syncthreads();
    }

#pragma unroll
    for (int i = 0; i < 8; i++) {
        int m = row0 + ty * 8 + i;
        if (m >= M_ROWS) continue;
#pragma unroll
        for (int j4 = 0; j4 < 2; j4++) {
            float2 c0 = unpk(acc2[i][j4*2 + 0]);
            float2 c1 = unpk(acc2[i][j4*2 + 1]);
            float4 v = make_float4(c0.x, c0.y, c1.x, c1.y);
            int n = col0 + tx * 8 + j4 * 4;
            if (QKV) {
                int t = n / E_DIM;
                int r = n - t * E_DIM;
                int h = r >> 6, d = r & 63;
                int b = m / S_LEN, s = m - b * S_LEN;
                size_t dst = (size_t)t * HSTRIDE
                           + (((size_t)b * NH + h) * S_LEN + s) * DH + d;
                *(float4*)&g_qkv[dst] = v;
            } else {
                *(float4*)&C[(size_t)m * N + n] = v;
            }
        }
    }
}

// ---------------------------------------------------------------------------
// RoPE (roll-by-1, per reference) in place on q,k patch tokens.
// One warp per (b, patch, t, h); lane handles d and d+32.
// ---------------------------------------------------------------------------
__global__ __launch_bounds__(256) void rope_kernel()
{
    const int gwarp = (blockIdx.x * blockDim.x + threadIdx.x) >> 5;
    const int lane  = threadIdx.x & 31;
    int h  = gwarp % 12;
    int w2 = gwarp / 12;
    int t  = w2 & 1;
    int w3 = w2 >> 1;
    int p  = w3 % 576;
    int b  = w3 / 576;
    if (b >= B_SZ) return;

    float* base = g_qkv + (size_t)t * HSTRIDE
                + (((size_t)b * NH + h) * S_LEN + (p + 1)) * DH;

    float v0 = base[lane];
    float v1 = base[lane + 32];
    const unsigned full = 0xffffffffu;
    float p0 = __shfl_sync(full, v0, (lane + 31) & 31);
    float p1 = __shfl_sync(full, v1, (lane + 31) & 31);

    float xc = (float)(p % 24) * (1.0f / 23.00000001f);
    float yc = (float)(p / 24) * (1.0f / 23.00000001f);
    int   fi = lane >> 1;
    float dv = expf(-(float)(2 * fi) * (9.210340371976184f / 32.0f));
    float ax = xc * dv, ay = yc * dv;

    base[lane]      = v0 * cosf(ax) + p0 * sinf(ax);
    base[lane + 32] = v1 * cosf(ay) + p1 * sinf(ay);
}

// ---------------------------------------------------------------------------
// Fused flash attention: per block one (b,h) and 128 query rows.
// Iterates 64-wide KV tiles with online softmax. fp32 via f32x2.
// Q^T/K^T/P^T stored transposed with XOR swizzle (conflict-free LDS.128).
// smem: qs[64][128] ks[64][64] vs[64][64] ps[64][128] = 96KB dynamic.
// ---------------------------------------------------------------------------
__device__ __forceinline__ int ix64(int r, int c) {
    return r * 64 + (((c >> 2) ^ ((r >> 2) & 15)) << 2) + (c & 3);
}
__device__ __forceinline__ int ix128(int r, int c) {
    return r * 128 + (((c >> 2) ^ ((r >> 2) & 15)) << 2) + (c & 3);
}

__global__ __launch_bounds__(256) void flash_attn()
{
    extern __shared__ float smf[];
    float* qs = smf;           // [d=64][i=128] transposed Q
    float* ks = smf + 8192;    // [d=64][j=64]  transposed K
    float* vs = smf + 12288;   // [j=64][d=64]
    float* ps = smf + 16384;   // [j=64][i=128] transposed P

    const int bh = blockIdx.y;
    const int b  = bh / NH, h = bh % NH;
    const int i0 = blockIdx.x * 128;
    const int tid = threadIdx.x;
    const int tx  = tid & 15;      // output d block: tx*4
    const int ty  = tid >> 4;      // row block: ty*8

    const float* qb = g_qkv + ((size_t)b * NH + h) * S_LEN * DH;
    const float* kb = qb + HSTRIDE;
    const float* vb = qb + 2 * HSTRIDE;

    // Load Q tile transposed (once per block)
#pragma unroll
    for (int it = 0; it < 8; it++) {
        int idx = tid + it * 256;      // 0..2047
        int r = idx >> 4;              // 0..127
        int c = (idx & 15) * 4;
        float4 v = make_float4(0.f, 0.f, 0.f, 0.f);
        if (i0 + r < S_LEN) v = *(const float4*)(qb + (size_t)(i0 + r) * DH + c);
        qs[ix128(c + 0, r)] = v.x;
        qs[ix128(c + 1, r)] = v.y;
        qs[ix128(c + 2, r)] = v.z;
        qs[ix128(c + 3, r)] = v.w;
    }

    u64 acc2[8][2] = {};
    float m_run[8], l_run[8];
#pragma unroll
    for (int i = 0; i < 8; i++) { m_run[i] = -1e30f; l_run[i] = 0.f; }

    for (int j0 = 0; j0 < 640; j0 += 64) {
        __syncthreads();   // prev PV done before overwriting ks/vs/ps
#pragma unroll
        for (int it = 0; it < 4; it++) {
            int idx = tid + it * 256;
            int r = idx >> 4;
            int c = (idx & 15) * 4;
            float4 kv = make_float4(0.f, 0.f, 0.f, 0.f), vv = kv;
            if (j0 + r < S_LEN) {
                kv = *(const float4*)(kb + (size_t)(j0 + r) * DH + c);
                vv = *(const float4*)(vb + (size_t)(j0 + r) * DH + c);
            }
            ks[ix64(c + 0, r)] = kv.x;
            ks[ix64(c + 1, r)] = kv.y;
            ks[ix64(c + 2, r)] = kv.z;
            ks[ix64(c + 3, r)] = kv.w;
            *(float4*)(vs + ix64(r, c)) = vv;
        }
        __syncthreads();

        // S = Q @ K^T  (8 rows x 4 cols per thread, f32x2-paired cols)
        u64 s2[8][2] = {};
#pragma unroll 8
        for (int k = 0; k < 64; k++) {
            float4 q0 = *(const float4*)(qs + ix128(k, ty * 8));
            float4 q1 = *(const float4*)(qs + ix128(k, ty * 8 + 4));
            ulonglong2 kp = *(const ulonglong2*)(ks + ix64(k, tx * 4));
            float qv[8] = {q0.x, q0.y, q0.z, q0.w, q1.x, q1.y, q1.z, q1.w};
#pragma unroll
            for (int ii = 0; ii < 8; ii++) {
                u64 qd = pack2(qv[ii], qv[ii]);
                s2[ii][0] = ffma2(qd, kp.x, s2[ii][0]);
                s2[ii][1] = ffma2(qd, kp.y, s2[ii][1]);
            }
        }

        // Online softmax update + store P transposed
        float fac[8];
#pragma unroll
        for (int ii = 0; ii < 8; ii++) {
            float2 sa = unpk(s2[ii][0]);
            float2 sb = unpk(s2[ii][1]);
            float sv[4] = {sa.x * 0.125f, sa.y * 0.125f, sb.x * 0.125f, sb.y * 0.125f};
#pragma unroll
            for (int jj = 0; jj < 4; jj++)
                if (j0 + tx * 4 + jj >= S_LEN) sv[jj] = -1e30f;
            float rm = fmaxf(fmaxf(sv[0], sv[1]), fmaxf(sv[2], sv[3]));
#pragma unroll
            for (int o = 8; o; o >>= 1) rm = fmaxf(rm, __shfl_xor_sync(0xffffffffu, rm, o));
            float mn = fmaxf(m_run[ii], rm);
            fac[ii] = __expf(m_run[ii] - mn);
            m_run[ii] = mn;
            float p0 = __expf(sv[0] - mn), p1 = __expf(sv[1] - mn);
            float p2 = __expf(sv[2] - mn), p3 = __expf(sv[3] - mn);
            float rs = p0 + p1 + p2 + p3;
#pragma unroll
            for (int o = 8; o; o >>= 1) rs += __shfl_xor_sync(0xffffffffu, rs, o);
            l_run[ii] = l_run[ii] * fac[ii] + rs;
            int col = ty * 8 + ii;
            ps[ix128(tx * 4 + 0, col)] = p0;
            ps[ix128(tx * 4 + 1, col)] = p1;
            ps[ix128(tx * 4 + 2, col)] = p2;
            ps[ix128(tx * 4 + 3, col)] = p3;
            u64 fd = pack2(fac[ii], fac[ii]);
            acc2[ii][0] = fmul2(acc2[ii][0], fd);
            acc2[ii][1] = fmul2(acc2[ii][1], fd);
        }
        __syncthreads();

        // acc += P @ V
#pragma unroll 8
        for (int k = 0; k < 64; k++) {
            ulonglong2 vp = *(const ulonglong2*)(vs + ix64(k, tx * 4));
            float4 p0 = *(const float4*)(ps + ix128(k, ty * 8));
            float4 p1 = *(const float4*)(ps + ix128(k, ty * 8 + 4));
            float pv[8] = {p0.x, p0.y, p0.z, p0.w, p1.x, p1.y, p1.z, p1.w};
#pragma unroll
            for (int ii = 0; ii < 8; ii++) {
                u64 pd = pack2(pv[ii], pv[ii]);
                acc2[ii][0] = ffma2(pd, vp.x, acc2[ii][0]);
                acc2[ii][1] = ffma2(pd, vp.y, acc2[ii][1]);
            }
        }
    }

    // Epilogue: normalize and write ctx[b][s][h*64+d]
#pragma unroll
    for (int ii = 0; ii < 8; ii++) {
        int i = i0 + ty * 8 + ii;
        if (i >= S_LEN) continue;
        float inv = 1.f / l_run[ii];
        float2 a = unpk(acc2[ii][0]);
        float2 c = unpk(acc2[ii][1]);
        float4 o = make_float4(a.x * inv, a.y * inv, c.x * inv, c.y * inv);
        *(float4*)&g_ctx[((size_t)b * S_LEN + i) * E_DIM + h * DH + tx * 4] = o;
    }
}

// ---------------------------------------------------------------------------
extern "C" void kernel_launch(void* const* d_in, const int* in_sizes, int n_in,
                              void* d_out, int out_size)
{
    (void)in_sizes; (void)n_in; (void)out_size;
    const float* x      = (const float*)d_in[0];
    const float* w_qkv  = (const float*)d_in[1];
    const float* w_proj = (const float*)d_in[2];
    float* out = (float*)d_out;

    float* ctx_ptr = nullptr;
    cudaGetSymbolAddress((void**)&ctx_ptr, g_ctx);

    cudaFuncSetAttribute(flash_attn, cudaFuncAttributeMaxDynamicSharedMemorySize, 98304);

    // 1) QKV projection -> g_qkv in [t][b][h][s][d]
    sgemm_f2<true><<<dim3(QKV_F / 128, (M_ROWS + 127) / 128), 256>>>(x, w_qkv, nullptr);

    // 2) RoPE in place on q,k patch tokens
    rope_kernel<<<(B_SZ * 576 * 2 * NH * 32) / 256, 256>>>();

    // 3) Fused attention -> g_ctx  (grid: 5 q-tiles x 384 (b,h) pairs)
    flash_attn<<<dim3(5, B_SZ * NH), 256, 98304>>>();

    // 4) Output projection
    sgemm_f2<false><<<dim3(E_DIM / 128, (M_ROWS + 127) / 128), 256>>>(ctx_ptr, w_proj, out);
}

// round 5
// speedup vs baseline: 1.4294x; 1.2766x over previous
#include <cuda_runtime.h>
#include <math.h>

#define B_SZ   32
#define S_LEN  577
#define E_DIM  768
#define NH     12
#define DH     64
#define M_ROWS (B_SZ * S_LEN)      // 18464
#define QKV_F  (3 * E_DIM)         // 2304
#define HSTRIDE ((size_t)B_SZ * NH * S_LEN * DH)   // per-(q/k/v) stride in g_qkv

// Scratch (device globals; allocation-free per harness rules)
__device__ float g_qkv[(size_t)3 * B_SZ * NH * S_LEN * DH];  // [t][b][h][s][d] ~170MB
__device__ float g_ctx[(size_t)M_ROWS * E_DIM];              // [b][s][h*64+d]  ~57MB

typedef unsigned long long u64;

// ---- packed fp32x2 helpers (exact IEEE fp32, 2x fma-pipe throughput) ----
__device__ __forceinline__ u64 pack2(float lo, float hi) {
    u64 r; asm("mov.b64 %0, {%1, %2};" : "=l"(r) : "f"(lo), "f"(hi)); return r;
}
__device__ __forceinline__ float2 unpk(u64 v) {
    float2 f; asm("mov.b64 {%0, %1}, %2;" : "=f"(f.x), "=f"(f.y) : "l"(v)); return f;
}
__device__ __forceinline__ u64 ffma2(u64 a, u64 b, u64 c) {
    u64 d; asm("fma.rn.f32x2 %0, %1, %2, %3;" : "=l"(d) : "l"(a), "l"(b), "l"(c)); return d;
}
__device__ __forceinline__ u64 fmul2(u64 a, u64 b) {
    u64 d; asm("mul.rn.f32x2 %0, %1, %2;" : "=l"(d) : "l"(a), "l"(b)); return d;
}

// ---------------------------------------------------------------------------
// GEMM: C[M,N] = A[M,K] @ W[N,K]^T. 128x128 tile, BK=16, 256 threads,
// 8x8 per thread (rows ty*4 & 64+ty*4, cols tx*4 & 64+tx*4).
// Double-buffered smem; A broadcast + register pack2; B vector LDS.128.
// QKV=true: writes g_qkv with [t][b][h][s][d] permutation.
// ---------------------------------------------------------------------------
template<bool QKV>
__global__ __launch_bounds__(256, 2) void sgemm_f2(const float* __restrict__ A,
                                                   const float* __restrict__ W,
                                                   float* __restrict__ C)
{
    const int N = QKV ? QKV_F : E_DIM;
    const int K = E_DIM;
    __shared__ float As[2][16][128];
    __shared__ float Bs[2][16][128];

    const int tid  = threadIdx.x;
    const int tx   = tid & 15;
    const int ty   = tid >> 4;
    const int row0 = blockIdx.y * 128;
    const int col0 = blockIdx.x * 128;
    const int lr   = tid >> 2;          // 0..63
    const int lc   = (tid & 3) * 4;     // 0,4,8,12

    u64 acc2[8][4] = {};

    float4 a0r, a1r, b0r, b1r;
    const float4 z4 = make_float4(0.f, 0.f, 0.f, 0.f);

#define LOAD_TILE(k0)                                                          \
    {                                                                          \
        int r0 = row0 + lr, r1 = row0 + 64 + lr;                               \
        a0r = (r0 < M_ROWS) ? *(const float4*)&A[(size_t)r0 * K + (k0) + lc] : z4; \
        a1r = (r1 < M_ROWS) ? *(const float4*)&A[(size_t)r1 * K + (k0) + lc] : z4; \
        b0r = *(const float4*)&W[(size_t)(col0 + lr) * K + (k0) + lc];         \
        b1r = *(const float4*)&W[(size_t)(col0 + 64 + lr) * K + (k0) + lc];    \
    }

#define STORE_TILE(s)                                                          \
    {                                                                          \
        As[s][lc + 0][lr] = a0r.x; As[s][lc + 1][lr] = a0r.y;                  \
        As[s][lc + 2][lr] = a0r.z; As[s][lc + 3][lr] = a0r.w;                  \
        As[s][lc + 0][64 + lr] = a1r.x; As[s][lc + 1][64 + lr] = a1r.y;        \
        As[s][lc + 2][64 + lr] = a1r.z; As[s][lc + 3][64 + lr] = a1r.w;        \
        Bs[s][lc + 0][lr] = b0r.x; Bs[s][lc + 1][lr] = b0r.y;                  \
        Bs[s][lc + 2][lr] = b0r.z; Bs[s][lc + 3][lr] = b0r.w;                  \
        Bs[s][lc + 0][64 + lr] = b1r.x; Bs[s][lc + 1][64 + lr] = b1r.y;        \
        Bs[s][lc + 2][64 + lr] = b1r.z; Bs[s][lc + 3][64 + lr] = b1r.w;        \
    }

    LOAD_TILE(0)
    STORE_TILE(0)
    __syncthreads();

    int s = 0;
    for (int k0 = 0; k0 < K; k0 += 16) {
        bool more = (k0 + 16 < K);
        if (more) LOAD_TILE(k0 + 16)

#pragma unroll
        for (int kk = 0; kk < 16; kk++) {
            float4 a0 = *(const float4*)&As[s][kk][ty * 4];
            float4 a1 = *(const float4*)&As[s][kk][64 + ty * 4];
            ulonglong2 bp0 = *(const ulonglong2*)&Bs[s][kk][tx * 4];
            ulonglong2 bp1 = *(const ulonglong2*)&Bs[s][kk][64 + tx * 4];
            u64 bp[4] = {bp0.x, bp0.y, bp1.x, bp1.y};
            float av[8] = {a0.x, a0.y, a0.z, a0.w, a1.x, a1.y, a1.z, a1.w};
#pragma unroll
            for (int i = 0; i < 8; i++) {
                u64 ad = pack2(av[i], av[i]);
#pragma unroll
                for (int j = 0; j < 4; j++)
                    acc2[i][j] = ffma2(ad, bp[j], acc2[i][j]);
            }
        }

        if (more) {
            STORE_TILE(s ^ 1)
            __syncthreads();
            s ^= 1;
        }
    }
#undef LOAD_TILE
#undef STORE_TILE

#pragma unroll
    for (int i = 0; i < 8; i++) {
        int m = row0 + ((i < 4) ? (ty * 4 + i) : (64 + ty * 4 + i - 4));
        if (m >= M_ROWS) continue;
#pragma unroll
        for (int half = 0; half < 2; half++) {
            float2 c0 = unpk(acc2[i][half * 2 + 0]);
            float2 c1 = unpk(acc2[i][half * 2 + 1]);
            float4 v = make_float4(c0.x, c0.y, c1.x, c1.y);
            int n = col0 + half * 64 + tx * 4;
            if (QKV) {
                int t = n / E_DIM;
                int r = n - t * E_DIM;
                int h = r >> 6, d = r & 63;
                int b = m / S_LEN, sидx = m - b * S_LEN;
                size_t dst = (size_t)t * HSTRIDE
                           + (((size_t)b * NH + h) * S_LEN + sидx) * DH + d;
                *(float4*)&g_qkv[dst] = v;
            } else {
                *(float4*)&C[(size_t)m * N + n] = v;
            }
        }
    }
}

// ---------------------------------------------------------------------------
// RoPE (roll-by-1, per reference) in place on q,k patch tokens.
// ---------------------------------------------------------------------------
__global__ __launch_bounds__(256) void rope_kernel()
{
    const int gwarp = (blockIdx.x * blockDim.x + threadIdx.x) >> 5;
    const int lane  = threadIdx.x & 31;
    int h  = gwarp % 12;
    int w2 = gwarp / 12;
    int t  = w2 & 1;
    int w3 = w2 >> 1;
    int p  = w3 % 576;
    int b  = w3 / 576;
    if (b >= B_SZ) return;

    float* base = g_qkv + (size_t)t * HSTRIDE
                + (((size_t)b * NH + h) * S_LEN + (p + 1)) * DH;

    float v0 = base[lane];
    float v1 = base[lane + 32];
    const unsigned full = 0xffffffffu;
    float p0 = __shfl_sync(full, v0, (lane + 31) & 31);
    float p1 = __shfl_sync(full, v1, (lane + 31) & 31);

    float xc = (float)(p % 24) * (1.0f / 23.00000001f);
    float yc = (float)(p / 24) * (1.0f / 23.00000001f);
    int   fi = lane >> 1;
    float dv = expf(-(float)(2 * fi) * (9.210340371976184f / 32.0f));
    float ax = xc * dv, ay = yc * dv;

    base[lane]      = v0 * cosf(ax) + p0 * sinf(ax);
    base[lane + 32] = v1 * cosf(ay) + p1 * sinf(ay);
}

// ---------------------------------------------------------------------------
// Fused flash attention: per block one (b,h) and 128 query rows.
// ---------------------------------------------------------------------------
__device__ __forceinline__ int ix64(int r, int c) {
    return r * 64 + (((c >> 2) ^ ((r >> 2) & 15)) << 2) + (c & 3);
}
__device__ __forceinline__ int ix128(int r, int c) {
    return r * 128 + (((c >> 2) ^ ((r >> 2) & 15)) << 2) + (c & 3);
}

__global__ __launch_bounds__(256) void flash_attn()
{
    extern __shared__ float smf[];
    float* qs = smf;           // [d=64][i=128] transposed Q
    float* ks = smf + 8192;    // [d=64][j=64]  transposed K
    float* vs = smf + 12288;   // [j=64][d=64]
    float* ps = smf + 16384;   // [j=64][i=128] transposed P

    const int bh = blockIdx.y;
    const int b  = bh / NH, h = bh % NH;
    const int i0 = blockIdx.x * 128;
    const int tid = threadIdx.x;
    const int tx  = tid & 15;
    const int ty  = tid >> 4;

    const float* qb = g_qkv + ((size_t)b * NH + h) * S_LEN * DH;
    const float* kb = qb + HSTRIDE;
    const float* vb = qb + 2 * HSTRIDE;

#pragma unroll
    for (int it = 0; it < 8; it++) {
        int idx = tid + it * 256;
        int r = idx >> 4;
        int c = (idx & 15) * 4;
        float4 v = make_float4(0.f, 0.f, 0.f, 0.f);
        if (i0 + r < S_LEN) v = *(const float4*)(qb + (size_t)(i0 + r) * DH + c);
        qs[ix128(c + 0, r)] = v.x;
        qs[ix128(c + 1, r)] = v.y;
        qs[ix128(c + 2, r)] = v.z;
        qs[ix128(c + 3, r)] = v.w;
    }

    u64 acc2[8][2] = {};
    float m_run[8], l_run[8];
#pragma unroll
    for (int i = 0; i < 8; i++) { m_run[i] = -1e30f; l_run[i] = 0.f; }

    for (int j0 = 0; j0 < 640; j0 += 64) {
        __syncthreads();
#pragma unroll
        for (int it = 0; it < 4; it++) {
            int idx = tid + it * 256;
            int r = idx >> 4;
            int c = (idx & 15) * 4;
            float4 kv = make_float4(0.f, 0.f, 0.f, 0.f), vv = kv;
            if (j0 + r < S_LEN) {
                kv = *(const float4*)(kb + (size_t)(j0 + r) * DH + c);
                vv = *(const float4*)(vb + (size_t)(j0 + r) * DH + c);
            }
            ks[ix64(c + 0, r)] = kv.x;
            ks[ix64(c + 1, r)] = kv.y;
            ks[ix64(c + 2, r)] = kv.z;
            ks[ix64(c + 3, r)] = kv.w;
            *(float4*)(vs + ix64(r, c)) = vv;
        }
        __syncthreads();

        u64 s2[8][2] = {};
#pragma unroll 8
        for (int k = 0; k < 64; k++) {
            float4 q0 = *(const float4*)(qs + ix128(k, ty * 8));
            float4 q1 = *(const float4*)(qs + ix128(k, ty * 8 + 4));
            ulonglong2 kp = *(const ulonglong2*)(ks + ix64(k, tx * 4));
            float qv[8] = {q0.x, q0.y, q0.z, q0.w, q1.x, q1.y, q1.z, q1.w};
#pragma unroll
            for (int ii = 0; ii < 8; ii++) {
                u64 qd = pack2(qv[ii], qv[ii]);
                s2[ii][0] = ffma2(qd, kp.x, s2[ii][0]);
                s2[ii][1] = ffma2(qd, kp.y, s2[ii][1]);
            }
        }

        float fac[8];
#pragma unroll
        for (int ii = 0; ii < 8; ii++) {
            float2 sa = unpk(s2[ii][0]);
            float2 sb = unpk(s2[ii][1]);
            float sv[4] = {sa.x * 0.125f, sa.y * 0.125f, sb.x * 0.125f, sb.y * 0.125f};
#pragma unroll
            for (int jj = 0; jj < 4; jj++)
                if (j0 + tx * 4 + jj >= S_LEN) sv[jj] = -1e30f;
            float rm = fmaxf(fmaxf(sv[0], sv[1]), fmaxf(sv[2], sv[3]));
#pragma unroll
            for (int o = 8; o; o >>= 1) rm = fmaxf(rm, __shfl_xor_sync(0xffffffffu, rm, o));
            float mn = fmaxf(m_run[ii], rm);
            fac[ii] = __expf(m_run[ii] - mn);
            m_run[ii] = mn;
            float p0 = __expf(sv[0] - mn), p1 = __expf(sv[1] - mn);
            float p2 = __expf(sv[2] - mn), p3 = __expf(sv[3] - mn);
            float rs = p0 + p1 + p2 + p3;
#pragma unroll
            for (int o = 8; o; o >>= 1) rs += __shfl_xor_sync(0xffffffffu, rs, o);
            l_run[ii] = l_run[ii] * fac[ii] + rs;
            int col = ty * 8 + ii;
            ps[ix128(tx * 4 + 0, col)] = p0;
            ps[ix128(tx * 4 + 1, col)] = p1;
            ps[ix128(tx * 4 + 2, col)] = p2;
            ps[ix128(tx * 4 + 3, col)] = p3;
            u64 fd = pack2(fac[ii], fac[ii]);
            acc2[ii][0] = fmul2(acc2[ii][0], fd);
            acc2[ii][1] = fmul2(acc2[ii][1], fd);
        }
        __syncthreads();

#pragma unroll 8
        for (int k = 0; k < 64; k++) {
            ulonglong2 vp = *(const ulonglong2*)(vs + ix64(k, tx * 4));
            float4 p0 = *(const float4*)(ps + ix128(k, ty * 8));
            float4 p1 = *(const float4*)(ps + ix128(k, ty * 8 + 4));
            float pv[8] = {p0.x, p0.y, p0.z, p0.w, p1.x, p1.y, p1.z, p1.w};
#pragma unroll
            for (int ii = 0; ii < 8; ii++) {
                u64 pd = pack2(pv[ii], pv[ii]);
                acc2[ii][0] = ffma2(pd, vp.x, acc2[ii][0]);
                acc2[ii][1] = ffma2(pd, vp.y, acc2[ii][1]);
            }
        }
    }

#pragma unroll
    for (int ii = 0; ii < 8; ii++) {
        int i = i0 + ty * 8 + ii;
        if (i >= S_LEN) continue;
        float inv = 1.f / l_run[ii];
        float2 a = unpk(acc2[ii][0]);
        float2 c = unpk(acc2[ii][1]);
        float4 o = make_float4(a.x * inv, a.y * inv, c.x * inv, c.y * inv);
        *(float4*)&g_ctx[((size_t)b * S_LEN + i) * E_DIM + h * DH + tx * 4] = o;
    }
}

// ---------------------------------------------------------------------------
extern "C" void kernel_launch(void* const* d_in, const int* in_sizes, int n_in,
                              void* d_out, int out_size)
{
    (void)in_sizes; (void)n_in; (void)out_size;
    const float* x      = (const float*)d_in[0];
    const float* w_qkv  = (const float*)d_in[1];
    const float* w_proj = (const float*)d_in[2];
    float* out = (float*)d_out;

    float* ctx_ptr = nullptr;
    cudaGetSymbolAddress((void**)&ctx_ptr, g_ctx);

    cudaFuncSetAttribute(flash_attn, cudaFuncAttributeMaxDynamicSharedMemorySize, 98304);

    // 1) QKV projection -> g_qkv in [t][b][h][s][d]
    sgemm_f2<true><<<dim3(QKV_F / 128, (M_ROWS + 127) / 128), 256>>>(x, w_qkv, nullptr);

    // 2) RoPE in place on q,k patch tokens
    rope_kernel<<<(B_SZ * 576 * 2 * NH * 32) / 256, 256>>>();

    // 3) Fused attention -> g_ctx  (grid: 5 q-tiles x 384 (b,h) pairs)
    flash_attn<<<dim3(5, B_SZ * NH), 256, 98304>>>();

    // 4) Output projection
    sgemm_f2<false><<<dim3(E_DIM / 128, (M_ROWS + 127) / 128), 256>>>(ctx_ptr, w_proj, out);
}

// round 7
// speedup vs baseline: 2.2124x; 1.5478x over previous
#include <cuda_runtime.h>
#include <cuda_bf16.h>
#include <math.h>
#include <stdint.h>

#define B_SZ   32
#define S_LEN  577
#define E_DIM  768
#define NH     12
#define DH     64
#define M_ROWS (B_SZ * S_LEN)      // 18464
#define QKV_F  (3 * E_DIM)         // 2304
#define HSTRIDE ((size_t)B_SZ * NH * S_LEN * DH)

// Scratch (device globals; allocation-free per harness rules)
__device__ float g_qkv[(size_t)3 * B_SZ * NH * S_LEN * DH];  // [t][b][h][s][d]
__device__ float g_ctx[(size_t)M_ROWS * E_DIM];              // [b][s][h*64+d]
__device__ __nv_bfloat16 g_ahi[(size_t)M_ROWS * E_DIM];
__device__ __nv_bfloat16 g_alo[(size_t)M_ROWS * E_DIM];
__device__ __nv_bfloat16 g_bhi[(size_t)QKV_F * E_DIM];
__device__ __nv_bfloat16 g_blo[(size_t)QKV_F * E_DIM];

typedef unsigned long long u64;

__device__ __forceinline__ uint32_t smem_to_u32(const void* p) {
    uint32_t a;
    asm("{ .reg .u64 t; cvta.to.shared.u64 t, %1; cvt.u32.u64 %0, t; }" : "=r"(a) : "l"(p));
    return a;
}

// ---- packed fp32x2 helpers (flash kernel) ----
__device__ __forceinline__ u64 pack2(float lo, float hi) {
    u64 r; asm("mov.b64 %0, {%1, %2};" : "=l"(r) : "f"(lo), "f"(hi)); return r;
}
__device__ __forceinline__ float2 unpk(u64 v) {
    float2 f; asm("mov.b64 {%0, %1}, %2;" : "=f"(f.x), "=f"(f.y) : "l"(v)); return f;
}
__device__ __forceinline__ u64 ffma2(u64 a, u64 b, u64 c) {
    u64 d; asm("fma.rn.f32x2 %0, %1, %2, %3;" : "=l"(d) : "l"(a), "l"(b), "l"(c)); return d;
}
__device__ __forceinline__ u64 fmul2(u64 a, u64 b) {
    u64 d; asm("mul.rn.f32x2 %0, %1, %2;" : "=l"(d) : "l"(a), "l"(b)); return d;
}

// ---- mma.sync helpers ----
#define LDSM4(r, addr)                                                         \
    asm volatile("ldmatrix.sync.aligned.m8n8.x4.shared.b16 {%0,%1,%2,%3}, [%4];" \
        : "=r"((r)[0]), "=r"((r)[1]), "=r"((r)[2]), "=r"((r)[3]) : "r"(addr))

#define MMA16816(d, a, b0, b1)                                                 \
    asm volatile("mma.sync.aligned.m16n8k16.row.col.f32.bf16.bf16.f32 "        \
        "{%0,%1,%2,%3}, {%4,%5,%6,%7}, {%8,%9}, {%0,%1,%2,%3};"                \
        : "+f"((d)[0]), "+f"((d)[1]), "+f"((d)[2]), "+f"((d)[3])               \
        : "r"((a)[0]), "r"((a)[1]), "r"((a)[2]), "r"((a)[3]), "r"(b0), "r"(b1))

// 16B-chunk swizzle within a [128][32]bf16 (=[128 rows][4 chunks]) array.
#define CHUNK_OFF(row, c) (((row) << 6) + ((((c) ^ (((row) >> 1) & 3))) << 4))

// ======================= bf16 hi/lo split ===================================
__global__ __launch_bounds__(256) void split_bf16(const float4* __restrict__ src,
                                                  uint2* __restrict__ hi,
                                                  uint2* __restrict__ lo, int n4)
{
    int i = blockIdx.x * blockDim.x + threadIdx.x;
    if (i >= n4) return;
    float4 v = src[i];
    __nv_bfloat16 h0 = __float2bfloat16(v.x), h1 = __float2bfloat16(v.y);
    __nv_bfloat16 h2 = __float2bfloat16(v.z), h3 = __float2bfloat16(v.w);
    __nv_bfloat16 l0 = __float2bfloat16(v.x - __bfloat162float(h0));
    __nv_bfloat16 l1 = __float2bfloat16(v.y - __bfloat162float(h1));
    __nv_bfloat16 l2 = __float2bfloat16(v.z - __bfloat162float(h2));
    __nv_bfloat16 l3 = __float2bfloat16(v.w - __bfloat162float(h3));
    uint2 hv, lv;
    hv.x = ((uint32_t)__bfloat16_as_ushort(h1) << 16) | __bfloat16_as_ushort(h0);
    hv.y = ((uint32_t)__bfloat16_as_ushort(h3) << 16) | __bfloat16_as_ushort(h2);
    lv.x = ((uint32_t)__bfloat16_as_ushort(l1) << 16) | __bfloat16_as_ushort(l0);
    lv.y = ((uint32_t)__bfloat16_as_ushort(l3) << 16) | __bfloat16_as_ushort(l2);
    hi[i] = hv;
    lo[i] = lv;
}

// ======================= HMMA GEMM (bf16x3 split) ===========================
// C[M,N] = A[M,768] @ W[N,768]^T. 128x128 CTA tile, BK=32, 8 warps (4 over M,
// 2 over N), warp tile 32x64. smem per stage: Ahi/Alo/Bhi/Blo 128x32 bf16
// (8KB each, 32KB/stage), double buffered. ldmatrix + mma.sync m16n8k16.
#define GEMM_SMEM (2 * 32768)

template<bool QKV>
__global__ __launch_bounds__(256, 1) void mma_gemm(float* __restrict__ C)
{
    extern __shared__ char sm[];
    const int tid  = threadIdx.x;
    const int lane = tid & 31;
    const int wid  = tid >> 5;
    const int wm   = wid & 3;          // 4 warps over M: 32 rows each
    const int wn   = wid >> 2;         // 2 warps over N: 64 cols each
    const int row0 = blockIdx.y * 128;
    const int col0 = blockIdx.x * 128;
    const uint32_t smem = smem_to_u32(sm);

    const int lr = tid >> 2;           // 0..63 (load row within pass)
    const int lc = tid & 3;            // 16B chunk

    float acc[2][8][4] = {};
    uint4 sAh[2], sAl[2], sBh[2], sBl[2];

    // ---- ldmatrix per-thread geometry (row fixed; chunk varies by kstep) ----
    const int arow[2] = { wm * 32 + 0 * 16 + (lane & 7) + ((lane >> 3) & 1) * 8,
                          wm * 32 + 1 * 16 + (lane & 7) + ((lane >> 3) & 1) * 8 };
    const int achk = lane >> 4;                       // 0/1 (k half)
    const int brow[4] = { wn * 64 + 0 * 16 + (lane & 7) + (lane >> 4) * 8,
                          wn * 64 + 1 * 16 + (lane & 7) + (lane >> 4) * 8,
                          wn * 64 + 2 * 16 + (lane & 7) + (lane >> 4) * 8,
                          wn * 64 + 3 * 16 + (lane & 7) + (lane >> 4) * 8 };
    const int bchk = (lane >> 3) & 1;                 // 0/1 (k half)

#define GLOAD(k0)                                                              \
    {                                                                          \
        _Pragma("unroll")                                                      \
        for (int p = 0; p < 2; p++) {                                          \
            int rA = row0 + lr + p * 64;                                       \
            size_t offA = (size_t)rA * E_DIM + (k0) + lc * 8;                  \
            if (rA < M_ROWS) {                                                 \
                sAh[p] = *(const uint4*)(g_ahi + offA);                        \
                sAl[p] = *(const uint4*)(g_alo + offA);                        \
            } else {                                                           \
                sAh[p] = make_uint4(0u,0u,0u,0u);                              \
                sAl[p] = make_uint4(0u,0u,0u,0u);                              \
            }                                                                  \
            size_t offB = (size_t)(col0 + lr + p * 64) * E_DIM + (k0) + lc * 8;\
            sBh[p] = *(const uint4*)(g_bhi + offB);                            \
            sBl[p] = *(const uint4*)(g_blo + offB);                            \
        }                                                                      \
    }

#define SSTORE(buf)                                                            \
    {                                                                          \
        char* base = sm + (buf) * 32768;                                       \
        _Pragma("unroll")                                                      \
        for (int p = 0; p < 2; p++) {                                          \
            int r = lr + p * 64;                                               \
            int co = CHUNK_OFF(r, lc);                                         \
            *(uint4*)(base + 0     + co) = sAh[p];                             \
            *(uint4*)(base + 8192  + co) = sAl[p];                             \
            *(uint4*)(base + 16384 + co) = sBh[p];                             \
            *(uint4*)(base + 24576 + co) = sBl[p];                             \
        }                                                                      \
    }

    GLOAD(0)
    SSTORE(0)
    __syncthreads();

    for (int s = 0; s < 24; s++) {
        const int buf = s & 1;
        if (s + 1 < 24) GLOAD((s + 1) * 32)

        const uint32_t sb = smem + buf * 32768;
#pragma unroll
        for (int ks = 0; ks < 2; ks++) {
            uint32_t ah[2][4], al[2][4];
#pragma unroll
            for (int i = 0; i < 2; i++) {
                uint32_t adr = sb + CHUNK_OFF(arow[i], ks * 2 + achk);
                LDSM4(ah[i], adr);
                LDSM4(al[i], adr + 8192);
            }
            uint32_t bh[4][4], bl[4][4];
#pragma unroll
            for (int g = 0; g < 4; g++) {
                uint32_t adr = sb + 16384 + CHUNK_OFF(brow[g], ks * 2 + bchk);
                LDSM4(bh[g], adr);
                LDSM4(bl[g], adr + 8192);
            }
#pragma unroll
            for (int i = 0; i < 2; i++)
#pragma unroll
                for (int g = 0; g < 4; g++)
#pragma unroll
                    for (int hh = 0; hh < 2; hh++) {
                        const int j = g * 2 + hh;
                        MMA16816(acc[i][j], ah[i], bh[g][hh*2], bh[g][hh*2+1]);
                        MMA16816(acc[i][j], ah[i], bl[g][hh*2], bl[g][hh*2+1]);
                        MMA16816(acc[i][j], al[i], bh[g][hh*2], bh[g][hh*2+1]);
                    }
        }

        if (s + 1 < 24) {
            SSTORE(buf ^ 1)
            __syncthreads();
        }
    }
#undef GLOAD
#undef SSTORE

    // Epilogue
#pragma unroll
    for (int i = 0; i < 2; i++)
#pragma unroll
        for (int half = 0; half < 2; half++) {
            int m = row0 + wm * 32 + i * 16 + (lane >> 2) + half * 8;
            if (m >= M_ROWS) continue;
            int bb = 0, sIdx = 0;
            if (QKV) { bb = m / S_LEN; sIdx = m - bb * S_LEN; }
#pragma unroll
            for (int j = 0; j < 8; j++) {
                int n = col0 + wn * 64 + j * 8 + (lane & 3) * 2;
                float2 v = make_float2(acc[i][j][half*2], acc[i][j][half*2+1]);
                if (QKV) {
                    int t = n / E_DIM, r = n - t * E_DIM;
                    int h = r >> 6, d = r & 63;
                    *(float2*)&g_qkv[(size_t)t * HSTRIDE
                        + (((size_t)bb * NH + h) * S_LEN + sIdx) * DH + d] = v;
                } else {
                    *(float2*)&C[(size_t)m * E_DIM + n] = v;
                }
            }
        }
}

// ======================= RoPE ===============================================
__global__ __launch_bounds__(256) void rope_kernel()
{
    const int gwarp = (blockIdx.x * blockDim.x + threadIdx.x) >> 5;
    const int lane  = threadIdx.x & 31;
    int h  = gwarp % 12;
    int w2 = gwarp / 12;
    int t  = w2 & 1;
    int w3 = w2 >> 1;
    int p  = w3 % 576;
    int b  = w3 / 576;
    if (b >= B_SZ) return;

    float* base = g_qkv + (size_t)t * HSTRIDE
                + (((size_t)b * NH + h) * S_LEN + (p + 1)) * DH;

    float v0 = base[lane];
    float v1 = base[lane + 32];
    const unsigned full = 0xffffffffu;
    float p0 = __shfl_sync(full, v0, (lane + 31) & 31);
    float p1 = __shfl_sync(full, v1, (lane + 31) & 31);

    float xc = (float)(p % 24) * (1.0f / 23.00000001f);
    float yc = (float)(p / 24) * (1.0f / 23.00000001f);
    int   fi = lane >> 1;
    float dv = expf(-(float)(2 * fi) * (9.210340371976184f / 32.0f));
    float ax = xc * dv, ay = yc * dv;

    base[lane]      = v0 * cosf(ax) + p0 * sinf(ax);
    base[lane + 32] = v1 * cosf(ay) + p1 * sinf(ay);
}

// ======================= fused flash attention ==============================
__device__ __forceinline__ int ix64(int r, int c) {
    return r * 64 + (((c >> 2) ^ ((r >> 2) & 15)) << 2) + (c & 3);
}
__device__ __forceinline__ int ix128(int r, int c) {
    return r * 128 + (((c >> 2) ^ ((r >> 2) & 15)) << 2) + (c & 3);
}

__global__ __launch_bounds__(256) void flash_attn()
{
    extern __shared__ float smf[];
    float* qs = smf;           // [d=64][i=128] transposed Q
    float* ks = smf + 8192;    // [d=64][j=64]  transposed K
    float* vs = smf + 12288;   // [j=64][d=64]
    float* ps = smf + 16384;   // [j=64][i=128] transposed P

    const int bh = blockIdx.y;
    const int b  = bh / NH, h = bh % NH;
    const int i0 = blockIdx.x * 128;
    const int tid = threadIdx.x;
    const int tx  = tid & 15;
    const int ty  = tid >> 4;

    const float* qb = g_qkv + ((size_t)b * NH + h) * S_LEN * DH;
    const float* kb = qb + HSTRIDE;
    const float* vb = qb + 2 * HSTRIDE;

#pragma unroll
    for (int it = 0; it < 8; it++) {
        int idx = tid + it * 256;
        int r = idx >> 4;
        int c = (idx & 15) * 4;
        float4 v = make_float4(0.f, 0.f, 0.f, 0.f);
        if (i0 + r < S_LEN) v = *(const float4*)(qb + (size_t)(i0 + r) * DH + c);
        qs[ix128(c + 0, r)] = v.x;
        qs[ix128(c + 1, r)] = v.y;
        qs[ix128(c + 2, r)] = v.z;
        qs[ix128(c + 3, r)] = v.w;
    }

    u64 acc2[8][2] = {};
    float m_run[8], l_run[8];
#pragma unroll
    for (int i = 0; i < 8; i++) { m_run[i] = -1e30f; l_run[i] = 0.f; }

    for (int j0 = 0; j0 < 640; j0 += 64) {
        __syncthreads();
#pragma unroll
        for (int it = 0; it < 4; it++) {
            int idx = tid + it * 256;
            int r = idx >> 4;
            int c = (idx & 15) * 4;
            float4 kv = make_float4(0.f, 0.f, 0.f, 0.f), vv = kv;
            if (j0 + r < S_LEN) {
                kv = *(const float4*)(kb + (size_t)(j0 + r) * DH + c);
                vv = *(const float4*)(vb + (size_t)(j0 + r) * DH + c);
            }
            ks[ix64(c + 0, r)] = kv.x;
            ks[ix64(c + 1, r)] = kv.y;
            ks[ix64(c + 2, r)] = kv.z;
            ks[ix64(c + 3, r)] = kv.w;
            *(float4*)(vs + ix64(r, c)) = vv;
        }
        __syncthreads();

        u64 s2[8][2] = {};
#pragma unroll 8
        for (int k = 0; k < 64; k++) {
            float4 q0 = *(const float4*)(qs + ix128(k, ty * 8));
            float4 q1 = *(const float4*)(qs + ix128(k, ty * 8 + 4));
            ulonglong2 kp = *(const ulonglong2*)(ks + ix64(k, tx * 4));
            float qv[8] = {q0.x, q0.y, q0.z, q0.w, q1.x, q1.y, q1.z, q1.w};
#pragma unroll
            for (int ii = 0; ii < 8; ii++) {
                u64 qd = pack2(qv[ii], qv[ii]);
                s2[ii][0] = ffma2(qd, kp.x, s2[ii][0]);
                s2[ii][1] = ffma2(qd, kp.y, s2[ii][1]);
            }
        }

        float fac[8];
#pragma unroll
        for (int ii = 0; ii < 8; ii++) {
            float2 sa = unpk(s2[ii][0]);
            float2 sb = unpk(s2[ii][1]);
            float sv[4] = {sa.x * 0.125f, sa.y * 0.125f, sb.x * 0.125f, sb.y * 0.125f};
#pragma unroll
            for (int jj = 0; jj < 4; jj++)
                if (j0 + tx * 4 + jj >= S_LEN) sv[jj] = -1e30f;
            float rm = fmaxf(fmaxf(sv[0], sv[1]), fmaxf(sv[2], sv[3]));
#pragma unroll
            for (int o = 8; o; o >>= 1) rm = fmaxf(rm, __shfl_xor_sync(0xffffffffu, rm, o));
            float mn = fmaxf(m_run[ii], rm);
            fac[ii] = __expf(m_run[ii] - mn);
            m_run[ii] = mn;
            float e0 = __expf(sv[0] - mn), e1 = __expf(sv[1] - mn);
            float e2 = __expf(sv[2] - mn), e3 = __expf(sv[3] - mn);
            float rs = e0 + e1 + e2 + e3;
#pragma unroll
            for (int o = 8; o; o >>= 1) rs += __shfl_xor_sync(0xffffffffu, rs, o);
            l_run[ii] = l_run[ii] * fac[ii] + rs;
            int col = ty * 8 + ii;
            ps[ix128(tx * 4 + 0, col)] = e0;
            ps[ix128(tx * 4 + 1, col)] = e1;
            ps[ix128(tx * 4 + 2, col)] = e2;
            ps[ix128(tx * 4 + 3, col)] = e3;
            u64 fd = pack2(fac[ii], fac[ii]);
            acc2[ii][0] = fmul2(acc2[ii][0], fd);
            acc2[ii][1] = fmul2(acc2[ii][1], fd);
        }
        __syncthreads();

#pragma unroll 8
        for (int k = 0; k < 64; k++) {
            ulonglong2 vp = *(const ulonglong2*)(vs + ix64(k, tx * 4));
            float4 pa = *(const float4*)(ps + ix128(k, ty * 8));
            float4 pb = *(const float4*)(ps + ix128(k, ty * 8 + 4));
            float pv[8] = {pa.x, pa.y, pa.z, pa.w, pb.x, pb.y, pb.z, pb.w};
#pragma unroll
            for (int ii = 0; ii < 8; ii++) {
                u64 pd = pack2(pv[ii], pv[ii]);
                acc2[ii][0] = ffma2(pd, vp.x, acc2[ii][0]);
                acc2[ii][1] = ffma2(pd, vp.y, acc2[ii][1]);
            }
        }
    }

#pragma unroll
    for (int ii = 0; ii < 8; ii++) {
        int i = i0 + ty * 8 + ii;
        if (i >= S_LEN) continue;
        float inv = 1.f / l_run[ii];
        float2 a = unpk(acc2[ii][0]);
        float2 c = unpk(acc2[ii][1]);
        float4 o = make_float4(a.x * inv, a.y * inv, c.x * inv, c.y * inv);
        *(float4*)&g_ctx[((size_t)b * S_LEN + i) * E_DIM + h * DH + tx * 4] = o;
    }
}

// ======================= launch =============================================
extern "C" void kernel_launch(void* const* d_in, const int* in_sizes, int n_in,
                              void* d_out, int out_size)
{
    (void)in_sizes; (void)n_in; (void)out_size;
    const float* x      = (const float*)d_in[0];
    const float* w_qkv  = (const float*)d_in[1];
    const float* w_proj = (const float*)d_in[2];
    float* out = (float*)d_out;

    void *ahi, *alo, *bhi, *blo, *ctx;
    cudaGetSymbolAddress(&ahi, g_ahi);
    cudaGetSymbolAddress(&alo, g_alo);
    cudaGetSymbolAddress(&bhi, g_bhi);
    cudaGetSymbolAddress(&blo, g_blo);
    cudaGetSymbolAddress(&ctx, g_ctx);

    cudaFuncSetAttribute(flash_attn, cudaFuncAttributeMaxDynamicSharedMemorySize, 98304);
    cudaFuncSetAttribute(mma_gemm<true>,  cudaFuncAttributeMaxDynamicSharedMemorySize, GEMM_SMEM);
    cudaFuncSetAttribute(mma_gemm<false>, cudaFuncAttributeMaxDynamicSharedMemorySize, GEMM_SMEM);

    const int MT = (M_ROWS + 127) / 128;   // 145

    // 1) split x and w_qkv into bf16 hi/lo
    {
        int n4 = M_ROWS * E_DIM / 4;
        split_bf16<<<(n4 + 255) / 256, 256>>>((const float4*)x, (uint2*)ahi, (uint2*)alo, n4);
        int w4 = QKV_F * E_DIM / 4;
        split_bf16<<<(w4 + 255) / 256, 256>>>((const float4*)w_qkv, (uint2*)bhi, (uint2*)blo, w4);
    }

    // 2) QKV projection on tensor cores -> g_qkv [t][b][h][s][d]
    mma_gemm<true><<<dim3(QKV_F / 128, MT), 256, GEMM_SMEM>>>(nullptr);

    // 3) RoPE in place on q,k patch tokens
    rope_kernel<<<(B_SZ * 576 * 2 * NH * 32) / 256, 256>>>();

    // 4) fused attention -> g_ctx
    flash_attn<<<dim3(5, B_SZ * NH), 256, 98304>>>();

    // 5) split ctx and w_proj
    {
        int n4 = M_ROWS * E_DIM / 4;
        split_bf16<<<(n4 + 255) / 256, 256>>>((const float4*)ctx, (uint2*)ahi, (uint2*)alo, n4);
        int w4 = E_DIM * E_DIM / 4;
        split_bf16<<<(w4 + 255) / 256, 256>>>((const float4*)w_proj, (uint2*)bhi, (uint2*)blo, w4);
    }

    // 6) output projection on tensor cores
    mma_gemm<false><<<dim3(E_DIM / 128, MT), 256, GEMM_SMEM>>>(out);
}

// round 8
// speedup vs baseline: 2.9997x; 1.3558x over previous
#include <cuda_runtime.h>
#include <cuda_bf16.h>
#include <math.h>
#include <stdint.h>

#define B_SZ   32
#define S_LEN  577
#define E_DIM  768
#define NH     12
#define DH     64
#define BH     (B_SZ * NH)         // 384
#define M_ROWS (B_SZ * S_LEN)      // 18464
#define QKV_F  (3 * E_DIM)         // 2304
#define SPAD   640
#define HSTRIDE ((size_t)B_SZ * NH * S_LEN * DH)

// Scratch (device globals; allocation-free per harness rules)
__device__ float g_qkv[(size_t)3 * B_SZ * NH * S_LEN * DH];  // [t][b][h][s][d]
__device__ float g_ctx[(size_t)M_ROWS * E_DIM];              // [b][s][h*64+d]
__device__ __nv_bfloat16 g_ahi[(size_t)M_ROWS * E_DIM];
__device__ __nv_bfloat16 g_alo[(size_t)M_ROWS * E_DIM];
__device__ __nv_bfloat16 g_bhi[(size_t)QKV_F * E_DIM];
__device__ __nv_bfloat16 g_blo[(size_t)QKV_F * E_DIM];
// flash operands
__device__ __nv_bfloat16 g_qhi[(size_t)BH * S_LEN * DH];
__device__ __nv_bfloat16 g_qlo[(size_t)BH * S_LEN * DH];
__device__ __nv_bfloat16 g_khi[(size_t)BH * S_LEN * DH];
__device__ __nv_bfloat16 g_klo[(size_t)BH * S_LEN * DH];
__device__ __nv_bfloat16 g_vthi[(size_t)BH * DH * SPAD];     // [bh][d][s]
__device__ __nv_bfloat16 g_vtlo[(size_t)BH * DH * SPAD];

__device__ __forceinline__ uint32_t smem_to_u32(const void* p) {
    uint32_t a;
    asm("{ .reg .u64 t; cvta.to.shared.u64 t, %1; cvt.u32.u64 %0, t; }" : "=r"(a) : "l"(p));
    return a;
}

// ---- mma.sync helpers ----
#define LDSM4(r, addr)                                                         \
    asm volatile("ldmatrix.sync.aligned.m8n8.x4.shared.b16 {%0,%1,%2,%3}, [%4];" \
        : "=r"((r)[0]), "=r"((r)[1]), "=r"((r)[2]), "=r"((r)[3]) : "r"(addr))

#define MMA16816(d, a, b0, b1)                                                 \
    asm volatile("mma.sync.aligned.m16n8k16.row.col.f32.bf16.bf16.f32 "        \
        "{%0,%1,%2,%3}, {%4,%5,%6,%7}, {%8,%9}, {%0,%1,%2,%3};"                \
        : "+f"((d)[0]), "+f"((d)[1]), "+f"((d)[2]), "+f"((d)[3])               \
        : "r"((a)[0]), "r"((a)[1]), "r"((a)[2]), "r"((a)[3]), "r"(b0), "r"(b1))

// 16B-chunk swizzles
#define CHUNK_OFF(row, c) (((row) << 6) + ((((c) ^ (((row) >> 1) & 3))) << 4)) // [r][32bf16]
#define CH8(row, c)       (((row) << 7) + ((((c) ^ ((row) & 7))) << 4))        // [r][64bf16]

__device__ __forceinline__ uint32_t pk2bf(float f0, float f1) {
    __nv_bfloat162 h = __floats2bfloat162_rn(f0, f1);   // .x = f0 (low), .y = f1 (high)
    return *(uint32_t*)&h;
}

// ======================= bf16 hi/lo split (GEMM inputs) =====================
__global__ __launch_bounds__(256) void split_bf16(const float4* __restrict__ src,
                                                  uint2* __restrict__ hi,
                                                  uint2* __restrict__ lo, int n4)
{
    int i = blockIdx.x * blockDim.x + threadIdx.x;
    if (i >= n4) return;
    float4 v = src[i];
    __nv_bfloat16 h0 = __float2bfloat16(v.x), h1 = __float2bfloat16(v.y);
    __nv_bfloat16 h2 = __float2bfloat16(v.z), h3 = __float2bfloat16(v.w);
    __nv_bfloat16 l0 = __float2bfloat16(v.x - __bfloat162float(h0));
    __nv_bfloat16 l1 = __float2bfloat16(v.y - __bfloat162float(h1));
    __nv_bfloat16 l2 = __float2bfloat16(v.z - __bfloat162float(h2));
    __nv_bfloat16 l3 = __float2bfloat16(v.w - __bfloat162float(h3));
    uint2 hv, lv;
    hv.x = ((uint32_t)__bfloat16_as_ushort(h1) << 16) | __bfloat16_as_ushort(h0);
    hv.y = ((uint32_t)__bfloat16_as_ushort(h3) << 16) | __bfloat16_as_ushort(h2);
    lv.x = ((uint32_t)__bfloat16_as_ushort(l1) << 16) | __bfloat16_as_ushort(l0);
    lv.y = ((uint32_t)__bfloat16_as_ushort(l3) << 16) | __bfloat16_as_ushort(l2);
    hi[i] = hv;
    lo[i] = lv;
}

// ======================= HMMA GEMM (bf16x3 split) — unchanged R7 ============
#define GEMM_SMEM (2 * 32768)

template<bool QKV>
__global__ __launch_bounds__(256, 1) void mma_gemm(float* __restrict__ C)
{
    extern __shared__ char sm[];
    const int tid  = threadIdx.x;
    const int lane = tid & 31;
    const int wid  = tid >> 5;
    const int wm   = wid & 3;
    const int wn   = wid >> 2;
    const int row0 = blockIdx.y * 128;
    const int col0 = blockIdx.x * 128;
    const uint32_t smem = smem_to_u32(sm);

    const int lr = tid >> 2;
    const int lc = tid & 3;

    float acc[2][8][4] = {};
    uint4 sAh[2], sAl[2], sBh[2], sBl[2];

    const int arow[2] = { wm * 32 + 0 * 16 + (lane & 7) + ((lane >> 3) & 1) * 8,
                          wm * 32 + 1 * 16 + (lane & 7) + ((lane >> 3) & 1) * 8 };
    const int achk = lane >> 4;
    const int brow[4] = { wn * 64 + 0 * 16 + (lane & 7) + (lane >> 4) * 8,
                          wn * 64 + 1 * 16 + (lane & 7) + (lane >> 4) * 8,
                          wn * 64 + 2 * 16 + (lane & 7) + (lane >> 4) * 8,
                          wn * 64 + 3 * 16 + (lane & 7) + (lane >> 4) * 8 };
    const int bchk = (lane >> 3) & 1;

#define GLOAD(k0)                                                              \
    {                                                                          \
        _Pragma("unroll")                                                      \
        for (int p = 0; p < 2; p++) {                                          \
            int rA = row0 + lr + p * 64;                                       \
            size_t offA = (size_t)rA * E_DIM + (k0) + lc * 8;                  \
            if (rA < M_ROWS) {                                                 \
                sAh[p] = *(const uint4*)(g_ahi + offA);                        \
                sAl[p] = *(const uint4*)(g_alo + offA);                        \
            } else {                                                           \
                sAh[p] = make_uint4(0u,0u,0u,0u);                              \
                sAl[p] = make_uint4(0u,0u,0u,0u);                              \
            }                                                                  \
            size_t offB = (size_t)(col0 + lr + p * 64) * E_DIM + (k0) + lc * 8;\
            sBh[p] = *(const uint4*)(g_bhi + offB);                            \
            sBl[p] = *(const uint4*)(g_blo + offB);                            \
        }                                                                      \
    }

#define SSTORE(buf)                                                            \
    {                                                                          \
        char* base = sm + (buf) * 32768;                                       \
        _Pragma("unroll")                                                      \
        for (int p = 0; p < 2; p++) {                                          \
            int r = lr + p * 64;                                               \
            int co = CHUNK_OFF(r, lc);                                         \
            *(uint4*)(base + 0     + co) = sAh[p];                             \
            *(uint4*)(base + 8192  + co) = sAl[p];                             \
            *(uint4*)(base + 16384 + co) = sBh[p];                             \
            *(uint4*)(base + 24576 + co) = sBl[p];                             \
        }                                                                      \
    }

    GLOAD(0)
    SSTORE(0)
    __syncthreads();

    for (int s = 0; s < 24; s++) {
        const int buf = s & 1;
        if (s + 1 < 24) GLOAD((s + 1) * 32)

        const uint32_t sb = smem + buf * 32768;
#pragma unroll
        for (int ks = 0; ks < 2; ks++) {
            uint32_t ah[2][4], al[2][4];
#pragma unroll
            for (int i = 0; i < 2; i++) {
                uint32_t adr = sb + CHUNK_OFF(arow[i], ks * 2 + achk);
                LDSM4(ah[i], adr);
                LDSM4(al[i], adr + 8192);
            }
            uint32_t bh[4][4], bl[4][4];
#pragma unroll
            for (int g = 0; g < 4; g++) {
                uint32_t adr = sb + 16384 + CHUNK_OFF(brow[g], ks * 2 + bchk);
                LDSM4(bh[g], adr);
                LDSM4(bl[g], adr + 8192);
            }
#pragma unroll
            for (int i = 0; i < 2; i++)
#pragma unroll
                for (int g = 0; g < 4; g++)
#pragma unroll
                    for (int hh = 0; hh < 2; hh++) {
                        const int j = g * 2 + hh;
                        MMA16816(acc[i][j], ah[i], bh[g][hh*2], bh[g][hh*2+1]);
                        MMA16816(acc[i][j], ah[i], bl[g][hh*2], bl[g][hh*2+1]);
                        MMA16816(acc[i][j], al[i], bh[g][hh*2], bh[g][hh*2+1]);
                    }
        }

        if (s + 1 < 24) {
            SSTORE(buf ^ 1)
            __syncthreads();
        }
    }
#undef GLOAD
#undef SSTORE

#pragma unroll
    for (int i = 0; i < 2; i++)
#pragma unroll
        for (int half = 0; half < 2; half++) {
            int m = row0 + wm * 32 + i * 16 + (lane >> 2) + half * 8;
            if (m >= M_ROWS) continue;
            int bb = 0, sIdx = 0;
            if (QKV) { bb = m / S_LEN; sIdx = m - bb * S_LEN; }
#pragma unroll
            for (int j = 0; j < 8; j++) {
                int n = col0 + wn * 64 + j * 8 + (lane & 3) * 2;
                float2 v = make_float2(acc[i][j][half*2], acc[i][j][half*2+1]);
                if (QKV) {
                    int t = n / E_DIM, r = n - t * E_DIM;
                    int h = r >> 6, d = r & 63;
                    *(float2*)&g_qkv[(size_t)t * HSTRIDE
                        + (((size_t)bb * NH + h) * S_LEN + sIdx) * DH + d] = v;
                } else {
                    *(float2*)&C[(size_t)m * E_DIM + n] = v;
                }
            }
        }
}

// ======================= convert: rope + split + V transpose ================
__global__ __launch_bounds__(256) void convert_rope_split()
{
    const int bh    = blockIdx.y;
    const int chunk = blockIdx.x;
    const int s0    = chunk * 64;
    const int tid   = threadIdx.x;
    const int wid   = tid >> 5, lane = tid & 31;
    const unsigned full = 0xffffffffu;

    // rope constants for this lane
    const int fi = lane >> 1;
    const float dv = expf(-(float)(2 * fi) * (9.210340371976184f / 32.0f));

#pragma unroll
    for (int t = 0; t < 2; t++) {
        __nv_bfloat16* dhi = t ? g_khi : g_qhi;
        __nv_bfloat16* dlo = t ? g_klo : g_qlo;
#pragma unroll
        for (int ps = 0; ps < 8; ps++) {
            int s = s0 + ps * 8 + wid;
            float v0 = 0.f, v1 = 0.f;
            bool valid = (s < S_LEN);
            if (valid) {
                const float* base = g_qkv + (size_t)t * HSTRIDE
                                  + ((size_t)bh * S_LEN + s) * DH;
                v0 = base[lane];
                v1 = base[lane + 32];
            }
            // rope (all lanes participate in shfl; result used only if s>=1)
            float p0 = __shfl_sync(full, v0, (lane + 31) & 31);
            float p1 = __shfl_sync(full, v1, (lane + 31) & 31);
            if (valid && s > 0) {
                int p = s - 1;
                float xc = (float)(p % 24) * (1.0f / 23.00000001f);
                float yc = (float)(p / 24) * (1.0f / 23.00000001f);
                float ax = xc * dv, ay = yc * dv;
                v0 = v0 * cosf(ax) + p0 * sinf(ax);
                v1 = v1 * cosf(ay) + p1 * sinf(ay);
            }
            if (valid) {
                size_t off = ((size_t)bh * S_LEN + s) * DH;
                __nv_bfloat16 h0 = __float2bfloat16(v0);
                __nv_bfloat16 h1 = __float2bfloat16(v1);
                dhi[off + lane]      = h0;
                dhi[off + lane + 32] = h1;
                dlo[off + lane]      = __float2bfloat16(v0 - __bfloat162float(h0));
                dlo[off + lane + 32] = __float2bfloat16(v1 - __bfloat162float(h1));
            }
        }
    }

    // V transpose + split: [s][d] -> [d][s]
    __shared__ float vbuf[64][65];
#pragma unroll
    for (int it = 0; it < 16; it++) {
        int idx = tid + it * 256;
        int r = idx >> 6, c = idx & 63;
        float val = (s0 + r < S_LEN)
            ? g_qkv[2 * HSTRIDE + ((size_t)bh * S_LEN + s0 + r) * DH + c] : 0.f;
        vbuf[c][r] = val;
    }
    __syncthreads();
    {
        int d = tid >> 2, grp = tid & 3;
        __nv_bfloat16 hh[16], ll[16];
#pragma unroll
        for (int i = 0; i < 16; i++) {
            float f = vbuf[d][grp * 16 + i];
            hh[i] = __float2bfloat16(f);
            ll[i] = __float2bfloat16(f - __bfloat162float(hh[i]));
        }
        size_t dst = (size_t)bh * (DH * SPAD) + (size_t)d * SPAD + s0 + grp * 16;
        *(uint4*)(g_vthi + dst)     = *(uint4*)hh;
        *(uint4*)(g_vthi + dst + 8) = *(uint4*)(hh + 8);
        *(uint4*)(g_vtlo + dst)     = *(uint4*)ll;
        *(uint4*)(g_vtlo + dst + 8) = *(uint4*)(ll + 8);
    }
}

// ======================= HMMA flash attention ===============================
// CTA: (i-tile of 128, bh). 8 warps, 16 q-rows each. KV tiles of 64.
#define FLASH_SMEM 65536

__global__ __launch_bounds__(256, 1) void flash_mma()
{
    extern __shared__ char sm[];
    const uint32_t smem = smem_to_u32(sm);
    const uint32_t qh32 = smem,          ql32 = smem + 16384;
    const uint32_t kh32 = smem + 32768,  kl32 = smem + 40960;
    const uint32_t vh32 = smem + 49152,  vl32 = smem + 57344;

    const int bh  = blockIdx.y;
    const int i0  = blockIdx.x * 128;
    const int tid = threadIdx.x;
    const int lane = tid & 31, wid = tid >> 5;

    // load Q (bf16 hi/lo), 128 rows x 64
#pragma unroll
    for (int it = 0; it < 4; it++) {
        int idx = tid + it * 256;
        int r = idx >> 3, c = idx & 7;
        int s = i0 + r;
        uint4 vh = make_uint4(0u,0u,0u,0u), vl = vh;
        if (s < S_LEN) {
            size_t off = ((size_t)bh * S_LEN + s) * DH + c * 8;
            vh = *(const uint4*)(g_qhi + off);
            vl = *(const uint4*)(g_qlo + off);
        }
        *(uint4*)(sm + CH8(r, c)) = vh;
        *(uint4*)(sm + 16384 + CH8(r, c)) = vl;
    }
    __syncthreads();

    // Q fragments (resident all loop)
    uint32_t qhf[4][4], qlf[4][4];
    {
        const int ar = wid * 16 + (lane & 7) + ((lane >> 3) & 1) * 8;
        const int ac = lane >> 4;
#pragma unroll
        for (int kt = 0; kt < 4; kt++) {
            LDSM4(qhf[kt], qh32 + CH8(ar, kt * 2 + ac));
            LDSM4(qlf[kt], ql32 + CH8(ar, kt * 2 + ac));
        }
    }

    float oacc[8][4] = {};
    float m0 = -1e30f, m1 = -1e30f, l0 = 0.f, l1 = 0.f;

    const int br = (lane & 7) + ((lane >> 4) << 3);
    const int bc = (lane >> 3) & 1;

    for (int t = 0; t < 10; t++) {
        const int j0 = t * 64;
        __syncthreads();
        // load K hi/lo [j][k] and Vt hi/lo [d][j]
#pragma unroll
        for (int it = 0; it < 2; it++) {
            int idx = tid + it * 256;
            int r = idx >> 3, c = idx & 7;
            int sj = j0 + r;
            uint4 a = make_uint4(0u,0u,0u,0u), b = a;
            if (sj < S_LEN) {
                size_t off = ((size_t)bh * S_LEN + sj) * DH + c * 8;
                a = *(const uint4*)(g_khi + off);
                b = *(const uint4*)(g_klo + off);
            }
            *(uint4*)(sm + 32768 + CH8(r, c)) = a;
            *(uint4*)(sm + 40960 + CH8(r, c)) = b;
            size_t voff = (size_t)bh * (DH * SPAD) + (size_t)r * SPAD + j0 + c * 8;
            *(uint4*)(sm + 49152 + CH8(r, c)) = *(const uint4*)(g_vthi + voff);
            *(uint4*)(sm + 57344 + CH8(r, c)) = *(const uint4*)(g_vtlo + voff);
        }
        __syncthreads();

        // S = Q K^T (x3 splits)
        float sacc[8][4] = {};
#pragma unroll
        for (int kt = 0; kt < 4; kt++) {
            uint32_t khf[4][4], klf[4][4];
#pragma unroll
            for (int g = 0; g < 4; g++) {
                uint32_t adr = CH8(g * 16 + br, kt * 2 + bc);
                LDSM4(khf[g], kh32 + adr);
                LDSM4(klf[g], kl32 + adr);
            }
#pragma unroll
            for (int g = 0; g < 4; g++)
#pragma unroll
                for (int hh = 0; hh < 2; hh++) {
                    const int j = g * 2 + hh;
                    MMA16816(sacc[j], qhf[kt], khf[g][hh*2], khf[g][hh*2+1]);
                    MMA16816(sacc[j], qhf[kt], klf[g][hh*2], klf[g][hh*2+1]);
                    MMA16816(sacc[j], qlf[kt], khf[g][hh*2], khf[g][hh*2+1]);
                }
        }

        // online softmax on fragments (rows lane>>2 and +8)
        float tm0 = -1e30f, tm1 = -1e30f;
#pragma unroll
        for (int nt = 0; nt < 8; nt++) {
            int jb = j0 + nt * 8 + (lane & 3) * 2;
            sacc[nt][0] = (jb     < S_LEN) ? sacc[nt][0] * 0.125f : -1e30f;
            sacc[nt][1] = (jb + 1 < S_LEN) ? sacc[nt][1] * 0.125f : -1e30f;
            sacc[nt][2] = (jb     < S_LEN) ? sacc[nt][2] * 0.125f : -1e30f;
            sacc[nt][3] = (jb + 1 < S_LEN) ? sacc[nt][3] * 0.125f : -1e30f;
            tm0 = fmaxf(tm0, fmaxf(sacc[nt][0], sacc[nt][1]));
            tm1 = fmaxf(tm1, fmaxf(sacc[nt][2], sacc[nt][3]));
        }
        tm0 = fmaxf(tm0, __shfl_xor_sync(0xffffffffu, tm0, 1));
        tm0 = fmaxf(tm0, __shfl_xor_sync(0xffffffffu, tm0, 2));
        tm1 = fmaxf(tm1, __shfl_xor_sync(0xffffffffu, tm1, 1));
        tm1 = fmaxf(tm1, __shfl_xor_sync(0xffffffffu, tm1, 2));
        float mn0 = fmaxf(m0, tm0), mn1 = fmaxf(m1, tm1);
        float f0 = __expf(m0 - mn0), f1 = __expf(m1 - mn1);
        m0 = mn0; m1 = mn1;

        float rs0 = 0.f, rs1 = 0.f;
#pragma unroll
        for (int nt = 0; nt < 8; nt++) {
            sacc[nt][0] = __expf(sacc[nt][0] - mn0);
            sacc[nt][1] = __expf(sacc[nt][1] - mn0);
            sacc[nt][2] = __expf(sacc[nt][2] - mn1);
            sacc[nt][3] = __expf(sacc[nt][3] - mn1);
            rs0 += sacc[nt][0] + sacc[nt][1];
            rs1 += sacc[nt][2] + sacc[nt][3];
        }
        rs0 += __shfl_xor_sync(0xffffffffu, rs0, 1);
        rs0 += __shfl_xor_sync(0xffffffffu, rs0, 2);
        rs1 += __shfl_xor_sync(0xffffffffu, rs1, 1);
        rs1 += __shfl_xor_sync(0xffffffffu, rs1, 2);
        l0 = l0 * f0 + rs0;
        l1 = l1 * f1 + rs1;

        // rescale O
#pragma unroll
        for (int nt = 0; nt < 8; nt++) {
            oacc[nt][0] *= f0; oacc[nt][1] *= f0;
            oacc[nt][2] *= f1; oacc[nt][3] *= f1;
        }

        // pack P into A-fragments (hi + residual lo)
        uint32_t pahi[4][4], palo[4][4];
#pragma unroll
        for (int kt = 0; kt < 4; kt++) {
            const int t0 = kt * 2, t1 = kt * 2 + 1;
            float v00 = sacc[t0][0], v01 = sacc[t0][1];
            float v02 = sacc[t0][2], v03 = sacc[t0][3];
            float v10 = sacc[t1][0], v11 = sacc[t1][1];
            float v12 = sacc[t1][2], v13 = sacc[t1][3];
            pahi[kt][0] = pk2bf(v00, v01);
            pahi[kt][1] = pk2bf(v02, v03);
            pahi[kt][2] = pk2bf(v10, v11);
            pahi[kt][3] = pk2bf(v12, v13);
            palo[kt][0] = pk2bf(v00 - __bfloat162float(__float2bfloat16(v00)),
                                v01 - __bfloat162float(__float2bfloat16(v01)));
            palo[kt][1] = pk2bf(v02 - __bfloat162float(__float2bfloat16(v02)),
                                v03 - __bfloat162float(__float2bfloat16(v03)));
            palo[kt][2] = pk2bf(v10 - __bfloat162float(__float2bfloat16(v10)),
                                v11 - __bfloat162float(__float2bfloat16(v11)));
            palo[kt][3] = pk2bf(v12 - __bfloat162float(__float2bfloat16(v12)),
                                v13 - __bfloat162float(__float2bfloat16(v13)));
        }

        // O += P V (x3 splits)
#pragma unroll
        for (int kt = 0; kt < 4; kt++) {
            uint32_t vhf[4][4], vlf[4][4];
#pragma unroll
            for (int g = 0; g < 4; g++) {
                uint32_t adr = CH8(g * 16 + br, kt * 2 + bc);
                LDSM4(vhf[g], vh32 + adr);
                LDSM4(vlf[g], vl32 + adr);
            }
#pragma unroll
            for (int g = 0; g < 4; g++)
#pragma unroll
                for (int hh = 0; hh < 2; hh++) {
                    const int j = g * 2 + hh;
                    MMA16816(oacc[j], pahi[kt], vhf[g][hh*2], vhf[g][hh*2+1]);
                    MMA16816(oacc[j], pahi[kt], vlf[g][hh*2], vlf[g][hh*2+1]);
                    MMA16816(oacc[j], palo[kt], vhf[g][hh*2], vhf[g][hh*2+1]);
                }
        }
    }

    // epilogue
    const float inv0 = 1.f / l0, inv1 = 1.f / l1;
    const int b = bh / NH, h = bh % NH;
    const int r0 = i0 + wid * 16 + (lane >> 2);
    const int r1 = r0 + 8;
#pragma unroll
    for (int nt = 0; nt < 8; nt++) {
        int d = nt * 8 + (lane & 3) * 2;
        if (r0 < S_LEN)
            *(float2*)&g_ctx[((size_t)b * S_LEN + r0) * E_DIM + h * DH + d]
                = make_float2(oacc[nt][0] * inv0, oacc[nt][1] * inv0);
        if (r1 < S_LEN)
            *(float2*)&g_ctx[((size_t)b * S_LEN + r1) * E_DIM + h * DH + d]
                = make_float2(oacc[nt][2] * inv1, oacc[nt][3] * inv1);
    }
}

// ======================= launch =============================================
extern "C" void kernel_launch(void* const* d_in, const int* in_sizes, int n_in,
                              void* d_out, int out_size)
{
    (void)in_sizes; (void)n_in; (void)out_size;
    const float* x      = (const float*)d_in[0];
    const float* w_qkv  = (const float*)d_in[1];
    const float* w_proj = (const float*)d_in[2];
    float* out = (float*)d_out;

    void *ahi, *alo, *bhi, *blo, *ctx;
    cudaGetSymbolAddress(&ahi, g_ahi);
    cudaGetSymbolAddress(&alo, g_alo);
    cudaGetSymbolAddress(&bhi, g_bhi);
    cudaGetSymbolAddress(&blo, g_blo);
    cudaGetSymbolAddress(&ctx, g_ctx);

    cudaFuncSetAttribute(mma_gemm<true>,  cudaFuncAttributeMaxDynamicSharedMemorySize, GEMM_SMEM);
    cudaFuncSetAttribute(mma_gemm<false>, cudaFuncAttributeMaxDynamicSharedMemorySize, GEMM_SMEM);
    cudaFuncSetAttribute(flash_mma, cudaFuncAttributeMaxDynamicSharedMemorySize, FLASH_SMEM);

    const int MT = (M_ROWS + 127) / 128;   // 145

    // 1) split x and w_qkv into bf16 hi/lo
    {
        int n4 = M_ROWS * E_DIM / 4;
        split_bf16<<<(n4 + 255) / 256, 256>>>((const float4*)x, (uint2*)ahi, (uint2*)alo, n4);
        int w4 = QKV_F * E_DIM / 4;
        split_bf16<<<(w4 + 255) / 256, 256>>>((const float4*)w_qkv, (uint2*)bhi, (uint2*)blo, w4);
    }

    // 2) QKV projection -> g_qkv [t][b][h][s][d]
    mma_gemm<true><<<dim3(QKV_F / 128, MT), 256, GEMM_SMEM>>>(nullptr);

    // 3) rope + bf16 split of q,k + V transpose/split
    convert_rope_split<<<dim3(10, BH), 256>>>();

    // 4) HMMA flash attention -> g_ctx
    flash_mma<<<dim3(5, BH), 256, FLASH_SMEM>>>();

    // 5) split ctx and w_proj
    {
        int n4 = M_ROWS * E_DIM / 4;
        split_bf16<<<(n4 + 255) / 256, 256>>>((const float4*)ctx, (uint2*)ahi, (uint2*)alo, n4);
        int w4 = E_DIM * E_DIM / 4;
        split_bf16<<<(w4 + 255) / 256, 256>>>((const float4*)w_proj, (uint2*)bhi, (uint2*)blo, w4);
    }

    // 6) output projection
    mma_gemm<false><<<dim3(E_DIM / 128, MT), 256, GEMM_SMEM>>>(out);
}

// round 9
// speedup vs baseline: 3.0480x; 1.0161x over previous
#include <cuda_runtime.h>
#include <cuda_bf16.h>
#include <math.h>
#include <stdint.h>

#define B_SZ   32
#define S_LEN  577
#define E_DIM  768
#define NH     12
#define DH     64
#define BH     (B_SZ * NH)         // 384
#define M_ROWS (B_SZ * S_LEN)      // 18464
#define QKV_F  (3 * E_DIM)         // 2304
#define SPAD   640
#define HSTRIDE ((size_t)B_SZ * NH * S_LEN * DH)

// Scratch (device globals; allocation-free per harness rules)
__device__ float g_qkv[(size_t)3 * B_SZ * NH * S_LEN * DH];  // [t][b][h][s][d]
__device__ __nv_bfloat16 g_ahi[(size_t)M_ROWS * E_DIM];
__device__ __nv_bfloat16 g_alo[(size_t)M_ROWS * E_DIM];
__device__ __nv_bfloat16 g_bhi[(size_t)QKV_F * E_DIM];
__device__ __nv_bfloat16 g_blo[(size_t)QKV_F * E_DIM];
// flash operands
__device__ __nv_bfloat16 g_qhi[(size_t)BH * S_LEN * DH];
__device__ __nv_bfloat16 g_qlo[(size_t)BH * S_LEN * DH];
__device__ __nv_bfloat16 g_khi[(size_t)BH * S_LEN * DH];
__device__ __nv_bfloat16 g_klo[(size_t)BH * S_LEN * DH];
__device__ __nv_bfloat16 g_vthi[(size_t)BH * DH * SPAD];     // [bh][d][s]
__device__ __nv_bfloat16 g_vtlo[(size_t)BH * DH * SPAD];

__device__ __forceinline__ uint32_t smem_to_u32(const void* p) {
    uint32_t a;
    asm("{ .reg .u64 t; cvta.to.shared.u64 t, %1; cvt.u32.u64 %0, t; }" : "=r"(a) : "l"(p));
    return a;
}

// ---- mma.sync helpers ----
#define LDSM4(r, addr)                                                         \
    asm volatile("ldmatrix.sync.aligned.m8n8.x4.shared.b16 {%0,%1,%2,%3}, [%4];" \
        : "=r"((r)[0]), "=r"((r)[1]), "=r"((r)[2]), "=r"((r)[3]) : "r"(addr))

#define MMA16816(d, a, b0, b1)                                                 \
    asm volatile("mma.sync.aligned.m16n8k16.row.col.f32.bf16.bf16.f32 "        \
        "{%0,%1,%2,%3}, {%4,%5,%6,%7}, {%8,%9}, {%0,%1,%2,%3};"                \
        : "+f"((d)[0]), "+f"((d)[1]), "+f"((d)[2]), "+f"((d)[3])               \
        : "r"((a)[0]), "r"((a)[1]), "r"((a)[2]), "r"((a)[3]), "r"(b0), "r"(b1))

// 16B-chunk swizzles
#define CHUNK_OFF(row, c) (((row) << 6) + ((((c) ^ (((row) >> 1) & 3))) << 4)) // [r][32bf16]
#define CH8(row, c)       (((row) << 7) + ((((c) ^ ((row) & 7))) << 4))        // [r][64bf16]

__device__ __forceinline__ uint32_t pk2bf(float f0, float f1) {
    __nv_bfloat162 h = __floats2bfloat162_rn(f0, f1);
    return *(uint32_t*)&h;
}

// ======================= bf16 hi/lo split (GEMM inputs) =====================
__global__ __launch_bounds__(256) void split_bf16(const float4* __restrict__ src,
                                                  uint2* __restrict__ hi,
                                                  uint2* __restrict__ lo, int n4)
{
    int i = blockIdx.x * blockDim.x + threadIdx.x;
    if (i >= n4) return;
    float4 v = src[i];
    __nv_bfloat16 h0 = __float2bfloat16(v.x), h1 = __float2bfloat16(v.y);
    __nv_bfloat16 h2 = __float2bfloat16(v.z), h3 = __float2bfloat16(v.w);
    __nv_bfloat16 l0 = __float2bfloat16(v.x - __bfloat162float(h0));
    __nv_bfloat16 l1 = __float2bfloat16(v.y - __bfloat162float(h1));
    __nv_bfloat16 l2 = __float2bfloat16(v.z - __bfloat162float(h2));
    __nv_bfloat16 l3 = __float2bfloat16(v.w - __bfloat162float(h3));
    uint2 hv, lv;
    hv.x = ((uint32_t)__bfloat16_as_ushort(h1) << 16) | __bfloat16_as_ushort(h0);
    hv.y = ((uint32_t)__bfloat16_as_ushort(h3) << 16) | __bfloat16_as_ushort(h2);
    lv.x = ((uint32_t)__bfloat16_as_ushort(l1) << 16) | __bfloat16_as_ushort(l0);
    lv.y = ((uint32_t)__bfloat16_as_ushort(l3) << 16) | __bfloat16_as_ushort(l2);
    hi[i] = hv;
    lo[i] = lv;
}

// ======================= HMMA GEMM (bf16x3, cp.async 3-stage) ===============
#define GEMM_STAGE 32768
#define GEMM_SMEM  (3 * GEMM_STAGE)

template<bool QKV>
__global__ __launch_bounds__(256) void mma_gemm(float* __restrict__ C)
{
    extern __shared__ char sm[];
    const int tid  = threadIdx.x;
    const int lane = tid & 31;
    const int wid  = tid >> 5;
    const int wm   = wid & 3;
    const int wn   = wid >> 2;
    const int row0 = blockIdx.y * 128;
    const int col0 = blockIdx.x * 128;
    const uint32_t smem = smem_to_u32(sm);

    const int lr = tid >> 2;
    const int lc = tid & 3;

    const int arow[2] = { wm * 32 + 0 * 16 + (lane & 7) + ((lane >> 3) & 1) * 8,
                          wm * 32 + 1 * 16 + (lane & 7) + ((lane >> 3) & 1) * 8 };
    const int achk = lane >> 4;
    const int brow[4] = { wn * 64 + 0 * 16 + (lane & 7) + (lane >> 4) * 8,
                          wn * 64 + 1 * 16 + (lane & 7) + (lane >> 4) * 8,
                          wn * 64 + 2 * 16 + (lane & 7) + (lane >> 4) * 8,
                          wn * 64 + 3 * 16 + (lane & 7) + (lane >> 4) * 8 };
    const int bchk = (lane >> 3) & 1;

#define ISSUE(s_)                                                              \
    {                                                                          \
        uint32_t sb_ = smem + ((s_) % 3) * GEMM_STAGE;                         \
        int k0_ = (s_) * 32;                                                   \
        _Pragma("unroll")                                                      \
        for (int p = 0; p < 2; p++) {                                          \
            int r = lr + p * 64;                                               \
            int rA = row0 + r;                                                 \
            uint32_t szA = (rA < M_ROWS) ? 16u : 0u;                           \
            size_t offA = (size_t)(rA < M_ROWS ? rA : 0) * E_DIM + k0_ + lc * 8; \
            size_t offB = (size_t)(col0 + r) * E_DIM + k0_ + lc * 8;           \
            uint32_t co = CHUNK_OFF(r, lc);                                    \
            asm volatile("cp.async.cg.shared.global [%0], [%1], 16, %2;"       \
                :: "r"(sb_ + co), "l"(g_ahi + offA), "r"(szA));                \
            asm volatile("cp.async.cg.shared.global [%0], [%1], 16, %2;"       \
                :: "r"(sb_ + 8192 + co), "l"(g_alo + offA), "r"(szA));         \
            asm volatile("cp.async.cg.shared.global [%0], [%1], 16;"           \
                :: "r"(sb_ + 16384 + co), "l"(g_bhi + offB));                  \
            asm volatile("cp.async.cg.shared.global [%0], [%1], 16;"           \
                :: "r"(sb_ + 24576 + co), "l"(g_blo + offB));                  \
        }                                                                      \
        asm volatile("cp.async.commit_group;");                                \
    }

    ISSUE(0)
    ISSUE(1)

    float acc[2][8][4] = {};

    for (int s = 0; s < 24; s++) {
        if (s + 1 < 24) asm volatile("cp.async.wait_group 1;");
        else            asm volatile("cp.async.wait_group 0;");
        __syncthreads();
        if (s + 2 < 24) ISSUE(s + 2)

        const uint32_t sb = smem + (s % 3) * GEMM_STAGE;
#pragma unroll
        for (int ks = 0; ks < 2; ks++) {
            uint32_t ah[2][4], al[2][4];
#pragma unroll
            for (int i = 0; i < 2; i++) {
                uint32_t adr = sb + CHUNK_OFF(arow[i], ks * 2 + achk);
                LDSM4(ah[i], adr);
                LDSM4(al[i], adr + 8192);
            }
            uint32_t bh[4][4], bl[4][4];
#pragma unroll
            for (int g = 0; g < 4; g++) {
                uint32_t adr = sb + 16384 + CHUNK_OFF(brow[g], ks * 2 + bchk);
                LDSM4(bh[g], adr);
                LDSM4(bl[g], adr + 8192);
            }
#pragma unroll
            for (int i = 0; i < 2; i++)
#pragma unroll
                for (int g = 0; g < 4; g++)
#pragma unroll
                    for (int hh = 0; hh < 2; hh++) {
                        const int j = g * 2 + hh;
                        MMA16816(acc[i][j], ah[i], bh[g][hh*2], bh[g][hh*2+1]);
                        MMA16816(acc[i][j], ah[i], bl[g][hh*2], bl[g][hh*2+1]);
                        MMA16816(acc[i][j], al[i], bh[g][hh*2], bh[g][hh*2+1]);
                    }
        }
    }
#undef ISSUE

#pragma unroll
    for (int i = 0; i < 2; i++)
#pragma unroll
        for (int half = 0; half < 2; half++) {
            int m = row0 + wm * 32 + i * 16 + (lane >> 2) + half * 8;
            if (m >= M_ROWS) continue;
            int bb = 0, sIdx = 0;
            if (QKV) { bb = m / S_LEN; sIdx = m - bb * S_LEN; }
#pragma unroll
            for (int j = 0; j < 8; j++) {
                int n = col0 + wn * 64 + j * 8 + (lane & 3) * 2;
                float2 v = make_float2(acc[i][j][half*2], acc[i][j][half*2+1]);
                if (QKV) {
                    int t = n / E_DIM, r = n - t * E_DIM;
                    int h = r >> 6, d = r & 63;
                    *(float2*)&g_qkv[(size_t)t * HSTRIDE
                        + (((size_t)bb * NH + h) * S_LEN + sIdx) * DH + d] = v;
                } else {
                    *(float2*)&C[(size_t)m * E_DIM + n] = v;
                }
            }
        }
}

// ======================= convert: rope + split + V transpose ================
__global__ __launch_bounds__(256) void convert_rope_split()
{
    const int bh    = blockIdx.y;
    const int chunk = blockIdx.x;
    const int s0    = chunk * 64;
    const int tid   = threadIdx.x;
    const int wid   = tid >> 5, lane = tid & 31;
    const unsigned full = 0xffffffffu;

    const int fi = lane >> 1;
    const float dv = expf(-(float)(2 * fi) * (9.210340371976184f / 32.0f));

#pragma unroll
    for (int t = 0; t < 2; t++) {
        __nv_bfloat16* dhi = t ? g_khi : g_qhi;
        __nv_bfloat16* dlo = t ? g_klo : g_qlo;
#pragma unroll
        for (int ps = 0; ps < 8; ps++) {
            int s = s0 + ps * 8 + wid;
            float v0 = 0.f, v1 = 0.f;
            bool valid = (s < S_LEN);
            if (valid) {
                const float* base = g_qkv + (size_t)t * HSTRIDE
                                  + ((size_t)bh * S_LEN + s) * DH;
                v0 = base[lane];
                v1 = base[lane + 32];
            }
            float p0 = __shfl_sync(full, v0, (lane + 31) & 31);
            float p1 = __shfl_sync(full, v1, (lane + 31) & 31);
            if (valid && s > 0) {
                int p = s - 1;
                float xc = (float)(p % 24) * (1.0f / 23.00000001f);
                float yc = (float)(p / 24) * (1.0f / 23.00000001f);
                float ax = xc * dv, ay = yc * dv;
                v0 = v0 * cosf(ax) + p0 * sinf(ax);
                v1 = v1 * cosf(ay) + p1 * sinf(ay);
            }
            if (valid) {
                size_t off = ((size_t)bh * S_LEN + s) * DH;
                __nv_bfloat16 h0 = __float2bfloat16(v0);
                __nv_bfloat16 h1 = __float2bfloat16(v1);
                dhi[off + lane]      = h0;
                dhi[off + lane + 32] = h1;
                dlo[off + lane]      = __float2bfloat16(v0 - __bfloat162float(h0));
                dlo[off + lane + 32] = __float2bfloat16(v1 - __bfloat162float(h1));
            }
        }
    }

    __shared__ float vbuf[64][65];
#pragma unroll
    for (int it = 0; it < 16; it++) {
        int idx = tid + it * 256;
        int r = idx >> 6, c = idx & 63;
        float val = (s0 + r < S_LEN)
            ? g_qkv[2 * HSTRIDE + ((size_t)bh * S_LEN + s0 + r) * DH + c] : 0.f;
        vbuf[c][r] = val;
    }
    __syncthreads();
    {
        int d = tid >> 2, grp = tid & 3;
        __nv_bfloat16 hh[16], ll[16];
#pragma unroll
        for (int i = 0; i < 16; i++) {
            float f = vbuf[d][grp * 16 + i];
            hh[i] = __float2bfloat16(f);
            ll[i] = __float2bfloat16(f - __bfloat162float(hh[i]));
        }
        size_t dst = (size_t)bh * (DH * SPAD) + (size_t)d * SPAD + s0 + grp * 16;
        *(uint4*)(g_vthi + dst)     = *(uint4*)hh;
        *(uint4*)(g_vthi + dst + 8) = *(uint4*)(hh + 8);
        *(uint4*)(g_vtlo + dst)     = *(uint4*)ll;
        *(uint4*)(g_vtlo + dst + 8) = *(uint4*)(ll + 8);
    }
}

// ======================= HMMA flash attention ===============================
#define FLASH_SMEM 65536

__global__ __launch_bounds__(256, 1) void flash_mma()
{
    extern __shared__ char sm[];
    const uint32_t smem = smem_to_u32(sm);
    const uint32_t qh32 = smem,          ql32 = smem + 16384;
    const uint32_t kh32 = smem + 32768,  kl32 = smem + 40960;
    const uint32_t vh32 = smem + 49152,  vl32 = smem + 57344;

    const int bh  = blockIdx.y;
    const int i0  = blockIdx.x * 128;
    const int tid = threadIdx.x;
    const int lane = tid & 31, wid = tid >> 5;

#pragma unroll
    for (int it = 0; it < 4; it++) {
        int idx = tid + it * 256;
        int r = idx >> 3, c = idx & 7;
        int s = i0 + r;
        uint4 vh = make_uint4(0u,0u,0u,0u), vl = vh;
        if (s < S_LEN) {
            size_t off = ((size_t)bh * S_LEN + s) * DH + c * 8;
            vh = *(const uint4*)(g_qhi + off);
            vl = *(const uint4*)(g_qlo + off);
        }
        *(uint4*)(sm + CH8(r, c)) = vh;
        *(uint4*)(sm + 16384 + CH8(r, c)) = vl;
    }
    __syncthreads();

    uint32_t qhf[4][4], qlf[4][4];
    {
        const int ar = wid * 16 + (lane & 7) + ((lane >> 3) & 1) * 8;
        const int ac = lane >> 4;
#pragma unroll
        for (int kt = 0; kt < 4; kt++) {
            LDSM4(qhf[kt], qh32 + CH8(ar, kt * 2 + ac));
            LDSM4(qlf[kt], ql32 + CH8(ar, kt * 2 + ac));
        }
    }

    float oacc[8][4] = {};
    float m0 = -1e30f, m1 = -1e30f, l0 = 0.f, l1 = 0.f;

    const int br = (lane & 7) + ((lane >> 4) << 3);
    const int bc = (lane >> 3) & 1;

    for (int t = 0; t < 10; t++) {
        const int j0 = t * 64;
        __syncthreads();
#pragma unroll
        for (int it = 0; it < 2; it++) {
            int idx = tid + it * 256;
            int r = idx >> 3, c = idx & 7;
            int sj = j0 + r;
            uint4 a = make_uint4(0u,0u,0u,0u), b = a;
            if (sj < S_LEN) {
                size_t off = ((size_t)bh * S_LEN + sj) * DH + c * 8;
                a = *(const uint4*)(g_khi + off);
                b = *(const uint4*)(g_klo + off);
            }
            *(uint4*)(sm + 32768 + CH8(r, c)) = a;
            *(uint4*)(sm + 40960 + CH8(r, c)) = b;
            size_t voff = (size_t)bh * (DH * SPAD) + (size_t)r * SPAD + j0 + c * 8;
            *(uint4*)(sm + 49152 + CH8(r, c)) = *(const uint4*)(g_vthi + voff);
            *(uint4*)(sm + 57344 + CH8(r, c)) = *(const uint4*)(g_vtlo + voff);
        }
        __syncthreads();

        float sacc[8][4] = {};
#pragma unroll
        for (int kt = 0; kt < 4; kt++) {
            uint32_t khf[4][4], klf[4][4];
#pragma unroll
            for (int g = 0; g < 4; g++) {
                uint32_t adr = CH8(g * 16 + br, kt * 2 + bc);
                LDSM4(khf[g], kh32 + adr);
                LDSM4(klf[g], kl32 + adr);
            }
#pragma unroll
            for (int g = 0; g < 4; g++)
#pragma unroll
                for (int hh = 0; hh < 2; hh++) {
                    const int j = g * 2 + hh;
                    MMA16816(sacc[j], qhf[kt], khf[g][hh*2], khf[g][hh*2+1]);
                    MMA16816(sacc[j], qhf[kt], klf[g][hh*2], klf[g][hh*2+1]);
                    MMA16816(sacc[j], qlf[kt], khf[g][hh*2], khf[g][hh*2+1]);
                }
        }

        float tm0 = -1e30f, tm1 = -1e30f;
#pragma unroll
        for (int nt = 0; nt < 8; nt++) {
            int jb = j0 + nt * 8 + (lane & 3) * 2;
            sacc[nt][0] = (jb     < S_LEN) ? sacc[nt][0] * 0.125f : -1e30f;
            sacc[nt][1] = (jb + 1 < S_LEN) ? sacc[nt][1] * 0.125f : -1e30f;
            sacc[nt][2] = (jb     < S_LEN) ? sacc[nt][2] * 0.125f : -1e30f;
            sacc[nt][3] = (jb + 1 < S_LEN) ? sacc[nt][3] * 0.125f : -1e30f;
            tm0 = fmaxf(tm0, fmaxf(sacc[nt][0], sacc[nt][1]));
            tm1 = fmaxf(tm1, fmaxf(sacc[nt][2], sacc[nt][3]));
        }
        tm0 = fmaxf(tm0, __shfl_xor_sync(0xffffffffu, tm0, 1));
        tm0 = fmaxf(tm0, __shfl_xor_sync(0xffffffffu, tm0, 2));
        tm1 = fmaxf(tm1, __shfl_xor_sync(0xffffffffu, tm1, 1));
        tm1 = fmaxf(tm1, __shfl_xor_sync(0xffffffffu, tm1, 2));
        float mn0 = fmaxf(m0, tm0), mn1 = fmaxf(m1, tm1);
        float f0 = __expf(m0 - mn0), f1 = __expf(m1 - mn1);
        m0 = mn0; m1 = mn1;

        float rs0 = 0.f, rs1 = 0.f;
#pragma unroll
        for (int nt = 0; nt < 8; nt++) {
            sacc[nt][0] = __expf(sacc[nt][0] - mn0);
            sacc[nt][1] = __expf(sacc[nt][1] - mn0);
            sacc[nt][2] = __expf(sacc[nt][2] - mn1);
            sacc[nt][3] = __expf(sacc[nt][3] - mn1);
            rs0 += sacc[nt][0] + sacc[nt][1];
            rs1 += sacc[nt][2] + sacc[nt][3];
        }
        rs0 += __shfl_xor_sync(0xffffffffu, rs0, 1);
        rs0 += __shfl_xor_sync(0xffffffffu, rs0, 2);
        rs1 += __shfl_xor_sync(0xffffffffu, rs1, 1);
        rs1 += __shfl_xor_sync(0xffffffffu, rs1, 2);
        l0 = l0 * f0 + rs0;
        l1 = l1 * f1 + rs1;

#pragma unroll
        for (int nt = 0; nt < 8; nt++) {
            oacc[nt][0] *= f0; oacc[nt][1] *= f0;
            oacc[nt][2] *= f1; oacc[nt][3] *= f1;
        }

        uint32_t pahi[4][4], palo[4][4];
#pragma unroll
        for (int kt = 0; kt < 4; kt++) {
            const int t0 = kt * 2, t1 = kt * 2 + 1;
            float v00 = sacc[t0][0], v01 = sacc[t0][1];
            float v02 = sacc[t0][2], v03 = sacc[t0][3];
            float v10 = sacc[t1][0], v11 = sacc[t1][1];
            float v12 = sacc[t1][2], v13 = sacc[t1][3];
            pahi[kt][0] = pk2bf(v00, v01);
            pahi[kt][1] = pk2bf(v02, v03);
            pahi[kt][2] = pk2bf(v10, v11);
            pahi[kt][3] = pk2bf(v12, v13);
            palo[kt][0] = pk2bf(v00 - __bfloat162float(__float2bfloat16(v00)),
                                v01 - __bfloat162float(__float2bfloat16(v01)));
            palo[kt][1] = pk2bf(v02 - __bfloat162float(__float2bfloat16(v02)),
                                v03 - __bfloat162float(__float2bfloat16(v03)));
            palo[kt][2] = pk2bf(v10 - __bfloat162float(__float2bfloat16(v10)),
                                v11 - __bfloat162float(__float2bfloat16(v11)));
            palo[kt][3] = pk2bf(v12 - __bfloat162float(__float2bfloat16(v12)),
                                v13 - __bfloat162float(__float2bfloat16(v13)));
        }

#pragma unroll
        for (int kt = 0; kt < 4; kt++) {
            uint32_t vhf[4][4], vlf[4][4];
#pragma unroll
            for (int g = 0; g < 4; g++) {
                uint32_t adr = CH8(g * 16 + br, kt * 2 + bc);
                LDSM4(vhf[g], vh32 + adr);
                LDSM4(vlf[g], vl32 + adr);
            }
#pragma unroll
            for (int g = 0; g < 4; g++)
#pragma unroll
                for (int hh = 0; hh < 2; hh++) {
                    const int j = g * 2 + hh;
                    MMA16816(oacc[j], pahi[kt], vhf[g][hh*2], vhf[g][hh*2+1]);
                    MMA16816(oacc[j], pahi[kt], vlf[g][hh*2], vlf[g][hh*2+1]);
                    MMA16816(oacc[j], palo[kt], vhf[g][hh*2], vhf[g][hh*2+1]);
                }
        }
    }

    // epilogue: write ctx directly as bf16 hi/lo (input A of out-proj GEMM)
    const float inv0 = 1.f / l0, inv1 = 1.f / l1;
    const int b = bh / NH, h = bh % NH;
    const int r0 = i0 + wid * 16 + (lane >> 2);
    const int r1 = r0 + 8;
#pragma unroll
    for (int nt = 0; nt < 8; nt++) {
        int d = nt * 8 + (lane & 3) * 2;
        if (r0 < S_LEN) {
            float o0 = oacc[nt][0] * inv0, o1 = oacc[nt][1] * inv0;
            size_t off = ((size_t)b * S_LEN + r0) * E_DIM + h * DH + d;
            *(uint32_t*)&g_ahi[off] = pk2bf(o0, o1);
            *(uint32_t*)&g_alo[off] = pk2bf(o0 - __bfloat162float(__float2bfloat16(o0)),
                                            o1 - __bfloat162float(__float2bfloat16(o1)));
        }
        if (r1 < S_LEN) {
            float o2 = oacc[nt][2] * inv1, o3 = oacc[nt][3] * inv1;
            size_t off = ((size_t)b * S_LEN + r1) * E_DIM + h * DH + d;
            *(uint32_t*)&g_ahi[off] = pk2bf(o2, o3);
            *(uint32_t*)&g_alo[off] = pk2bf(o2 - __bfloat162float(__float2bfloat16(o2)),
                                            o3 - __bfloat162float(__float2bfloat16(o3)));
        }
    }
}

// ======================= launch =============================================
extern "C" void kernel_launch(void* const* d_in, const int* in_sizes, int n_in,
                              void* d_out, int out_size)
{
    (void)in_sizes; (void)n_in; (void)out_size;
    const float* x      = (const float*)d_in[0];
    const float* w_qkv  = (const float*)d_in[1];
    const float* w_proj = (const float*)d_in[2];
    float* out = (float*)d_out;

    void *ahi, *alo, *bhi, *blo;
    cudaGetSymbolAddress(&ahi, g_ahi);
    cudaGetSymbolAddress(&alo, g_alo);
    cudaGetSymbolAddress(&bhi, g_bhi);
    cudaGetSymbolAddress(&blo, g_blo);

    cudaFuncSetAttribute(mma_gemm<true>,  cudaFuncAttributeMaxDynamicSharedMemorySize, GEMM_SMEM);
    cudaFuncSetAttribute(mma_gemm<false>, cudaFuncAttributeMaxDynamicSharedMemorySize, GEMM_SMEM);
    cudaFuncSetAttribute(flash_mma, cudaFuncAttributeMaxDynamicSharedMemorySize, FLASH_SMEM);

    const int MT = (M_ROWS + 127) / 128;   // 145

    // 1) split x and w_qkv into bf16 hi/lo
    {
        int n4 = M_ROWS * E_DIM / 4;
        split_bf16<<<(n4 + 255) / 256, 256>>>((const float4*)x, (uint2*)ahi, (uint2*)alo, n4);
        int w4 = QKV_F * E_DIM / 4;
        split_bf16<<<(w4 + 255) / 256, 256>>>((const float4*)w_qkv, (uint2*)bhi, (uint2*)blo, w4);
    }

    // 2) QKV projection -> g_qkv [t][b][h][s][d]
    mma_gemm<true><<<dim3(QKV_F / 128, MT), 256, GEMM_SMEM>>>(nullptr);

    // 3) rope + bf16 split of q,k + V transpose/split
    convert_rope_split<<<dim3(10, BH), 256>>>();

    // 4) HMMA flash attention -> ctx written as bf16 hi/lo into g_ahi/g_alo
    flash_mma<<<dim3(5, BH), 256, FLASH_SMEM>>>();

    // 5) split w_proj only (ctx hi/lo already produced by flash epilogue)
    {
        int w4 = E_DIM * E_DIM / 4;
        split_bf16<<<(w4 + 255) / 256, 256>>>((const float4*)w_proj, (uint2*)bhi, (uint2*)blo, w4);
    }

    // 6) output projection
    mma_gemm<false><<<dim3(E_DIM / 128, MT), 256, GEMM_SMEM>>>(out);
}

// round 10
// speedup vs baseline: 3.3497x; 1.0990x over previous
#include <cuda_runtime.h>
#include <cuda_bf16.h>
#include <math.h>
#include <stdint.h>

#define B_SZ   32
#define S_LEN  577
#define E_DIM  768
#define NH     12
#define DH     64
#define BH     (B_SZ * NH)         // 384
#define M_ROWS (B_SZ * S_LEN)      // 18464
#define QKV_F  (3 * E_DIM)         // 2304
#define SPAD   640
#define HSTRIDE ((size_t)B_SZ * NH * S_LEN * DH)

// Scratch (device globals; allocation-free per harness rules)
__device__ float g_qkv[(size_t)3 * B_SZ * NH * S_LEN * DH];  // [t][b][h][s][d]
__device__ __nv_bfloat16 g_ahi[(size_t)M_ROWS * E_DIM];
__device__ __nv_bfloat16 g_alo[(size_t)M_ROWS * E_DIM];
__device__ __nv_bfloat16 g_bhi[(size_t)QKV_F * E_DIM];
__device__ __nv_bfloat16 g_blo[(size_t)QKV_F * E_DIM];
// flash operands
__device__ __nv_bfloat16 g_qhi[(size_t)BH * S_LEN * DH];
__device__ __nv_bfloat16 g_qlo[(size_t)BH * S_LEN * DH];
__device__ __nv_bfloat16 g_khi[(size_t)BH * S_LEN * DH];
__device__ __nv_bfloat16 g_klo[(size_t)BH * S_LEN * DH];
__device__ __nv_bfloat16 g_vthi[(size_t)BH * DH * SPAD];     // [bh][d][s]
__device__ __nv_bfloat16 g_vtlo[(size_t)BH * DH * SPAD];

__device__ __forceinline__ uint32_t smem_to_u32(const void* p) {
    uint32_t a;
    asm("{ .reg .u64 t; cvta.to.shared.u64 t, %1; cvt.u32.u64 %0, t; }" : "=r"(a) : "l"(p));
    return a;
}

// ---- mma.sync helpers ----
#define LDSM4(r, addr)                                                         \
    asm volatile("ldmatrix.sync.aligned.m8n8.x4.shared.b16 {%0,%1,%2,%3}, [%4];" \
        : "=r"((r)[0]), "=r"((r)[1]), "=r"((r)[2]), "=r"((r)[3]) : "r"(addr))

#define MMA16816(d, a, b0, b1)                                                 \
    asm volatile("mma.sync.aligned.m16n8k16.row.col.f32.bf16.bf16.f32 "        \
        "{%0,%1,%2,%3}, {%4,%5,%6,%7}, {%8,%9}, {%0,%1,%2,%3};"                \
        : "+f"((d)[0]), "+f"((d)[1]), "+f"((d)[2]), "+f"((d)[3])               \
        : "r"((a)[0]), "r"((a)[1]), "r"((a)[2]), "r"((a)[3]), "r"(b0), "r"(b1))

// 16B-chunk swizzles
#define CHUNK_OFF(row, c) (((row) << 6) + ((((c) ^ (((row) >> 1) & 3))) << 4)) // [r][32bf16]
#define CH8(row, c)       (((row) << 7) + ((((c) ^ ((row) & 7))) << 4))        // [r][64bf16]

__device__ __forceinline__ uint32_t pk2bf(float f0, float f1) {
    __nv_bfloat162 h = __floats2bfloat162_rn(f0, f1);
    return *(uint32_t*)&h;
}

// ======================= bf16 hi/lo split (GEMM inputs) =====================
__global__ __launch_bounds__(256) void split_bf16(const float4* __restrict__ src,
                                                  uint2* __restrict__ hi,
                                                  uint2* __restrict__ lo, int n4)
{
    int i = blockIdx.x * blockDim.x + threadIdx.x;
    if (i >= n4) return;
    float4 v = src[i];
    __nv_bfloat16 h0 = __float2bfloat16(v.x), h1 = __float2bfloat16(v.y);
    __nv_bfloat16 h2 = __float2bfloat16(v.z), h3 = __float2bfloat16(v.w);
    __nv_bfloat16 l0 = __float2bfloat16(v.x - __bfloat162float(h0));
    __nv_bfloat16 l1 = __float2bfloat16(v.y - __bfloat162float(h1));
    __nv_bfloat16 l2 = __float2bfloat16(v.z - __bfloat162float(h2));
    __nv_bfloat16 l3 = __float2bfloat16(v.w - __bfloat162float(h3));
    uint2 hv, lv;
    hv.x = ((uint32_t)__bfloat16_as_ushort(h1) << 16) | __bfloat16_as_ushort(h0);
    hv.y = ((uint32_t)__bfloat16_as_ushort(h3) << 16) | __bfloat16_as_ushort(h2);
    lv.x = ((uint32_t)__bfloat16_as_ushort(l1) << 16) | __bfloat16_as_ushort(l0);
    lv.y = ((uint32_t)__bfloat16_as_ushort(l3) << 16) | __bfloat16_as_ushort(l2);
    hi[i] = hv;
    lo[i] = lv;
}

// ======================= HMMA GEMM (bf16x3, cp.async 3-stage) ===============
#define GEMM_STAGE 32768
#define GEMM_SMEM  (3 * GEMM_STAGE)

template<bool QKV>
__global__ __launch_bounds__(256) void mma_gemm(float* __restrict__ C)
{
    extern __shared__ char sm[];
    const int tid  = threadIdx.x;
    const int lane = tid & 31;
    const int wid  = tid >> 5;
    const int wm   = wid & 3;
    const int wn   = wid >> 2;
    const int row0 = blockIdx.y * 128;
    const int col0 = blockIdx.x * 128;
    const uint32_t smem = smem_to_u32(sm);

    const int lr = tid >> 2;
    const int lc = tid & 3;

    const int arow[2] = { wm * 32 + 0 * 16 + (lane & 7) + ((lane >> 3) & 1) * 8,
                          wm * 32 + 1 * 16 + (lane & 7) + ((lane >> 3) & 1) * 8 };
    const int achk = lane >> 4;
    const int brow[4] = { wn * 64 + 0 * 16 + (lane & 7) + (lane >> 4) * 8,
                          wn * 64 + 1 * 16 + (lane & 7) + (lane >> 4) * 8,
                          wn * 64 + 2 * 16 + (lane & 7) + (lane >> 4) * 8,
                          wn * 64 + 3 * 16 + (lane & 7) + (lane >> 4) * 8 };
    const int bchk = (lane >> 3) & 1;

#define ISSUE(s_)                                                              \
    {                                                                          \
        uint32_t sb_ = smem + ((s_) % 3) * GEMM_STAGE;                         \
        int k0_ = (s_) * 32;                                                   \
        _Pragma("unroll")                                                      \
        for (int p = 0; p < 2; p++) {                                          \
            int r = lr + p * 64;                                               \
            int rA = row0 + r;                                                 \
            uint32_t szA = (rA < M_ROWS) ? 16u : 0u;                           \
            size_t offA = (size_t)(rA < M_ROWS ? rA : 0) * E_DIM + k0_ + lc * 8; \
            size_t offB = (size_t)(col0 + r) * E_DIM + k0_ + lc * 8;           \
            uint32_t co = CHUNK_OFF(r, lc);                                    \
            asm volatile("cp.async.cg.shared.global [%0], [%1], 16, %2;"       \
                :: "r"(sb_ + co), "l"(g_ahi + offA), "r"(szA));                \
            asm volatile("cp.async.cg.shared.global [%0], [%1], 16, %2;"       \
                :: "r"(sb_ + 8192 + co), "l"(g_alo + offA), "r"(szA));         \
            asm volatile("cp.async.cg.shared.global [%0], [%1], 16;"           \
                :: "r"(sb_ + 16384 + co), "l"(g_bhi + offB));                  \
            asm volatile("cp.async.cg.shared.global [%0], [%1], 16;"           \
                :: "r"(sb_ + 24576 + co), "l"(g_blo + offB));                  \
        }                                                                      \
        asm volatile("cp.async.commit_group;");                                \
    }

    ISSUE(0)
    ISSUE(1)

    float acc[2][8][4] = {};

    for (int s = 0; s < 24; s++) {
        if (s + 1 < 24) asm volatile("cp.async.wait_group 1;");
        else            asm volatile("cp.async.wait_group 0;");
        __syncthreads();
        if (s + 2 < 24) ISSUE(s + 2)

        const uint32_t sb = smem + (s % 3) * GEMM_STAGE;
#pragma unroll
        for (int ks = 0; ks < 2; ks++) {
            uint32_t ah[2][4], al[2][4];
#pragma unroll
            for (int i = 0; i < 2; i++) {
                uint32_t adr = sb + CHUNK_OFF(arow[i], ks * 2 + achk);
                LDSM4(ah[i], adr);
                LDSM4(al[i], adr + 8192);
            }
            uint32_t bh[4][4], bl[4][4];
#pragma unroll
            for (int g = 0; g < 4; g++) {
                uint32_t adr = sb + 16384 + CHUNK_OFF(brow[g], ks * 2 + bchk);
                LDSM4(bh[g], adr);
                LDSM4(bl[g], adr + 8192);
            }
#pragma unroll
            for (int i = 0; i < 2; i++)
#pragma unroll
                for (int g = 0; g < 4; g++)
#pragma unroll
                    for (int hh = 0; hh < 2; hh++) {
                        const int j = g * 2 + hh;
                        MMA16816(acc[i][j], ah[i], bh[g][hh*2], bh[g][hh*2+1]);
                        MMA16816(acc[i][j], ah[i], bl[g][hh*2], bl[g][hh*2+1]);
                        MMA16816(acc[i][j], al[i], bh[g][hh*2], bh[g][hh*2+1]);
                    }
        }
    }
#undef ISSUE

#pragma unroll
    for (int i = 0; i < 2; i++)
#pragma unroll
        for (int half = 0; half < 2; half++) {
            int m = row0 + wm * 32 + i * 16 + (lane >> 2) + half * 8;
            if (m >= M_ROWS) continue;
            int bb = 0, sIdx = 0;
            if (QKV) { bb = m / S_LEN; sIdx = m - bb * S_LEN; }
#pragma unroll
            for (int j = 0; j < 8; j++) {
                int n = col0 + wn * 64 + j * 8 + (lane & 3) * 2;
                float2 v = make_float2(acc[i][j][half*2], acc[i][j][half*2+1]);
                if (QKV) {
                    int t = n / E_DIM, r = n - t * E_DIM;
                    int h = r >> 6, d = r & 63;
                    *(float2*)&g_qkv[(size_t)t * HSTRIDE
                        + (((size_t)bb * NH + h) * S_LEN + sIdx) * DH + d] = v;
                } else {
                    *(float2*)&C[(size_t)m * E_DIM + n] = v;
                }
            }
        }
}

// ======================= convert: rope (table) + split + V transpose ========
__global__ __launch_bounds__(256) void convert_rope_split()
{
    const int bh    = blockIdx.y;
    const int chunk = blockIdx.x;
    const int s0    = chunk * 64;
    const int tid   = threadIdx.x;
    const int wid   = tid >> 5, lane = tid & 31;
    const unsigned full = 0xffffffffu;

    // trig tables: ct/st[v][fi] = cos/sin( (v/23.00000001) * exp(-2*fi*ln1e4/32) )
    __shared__ float ct[24][16], st[24][16];
    for (int e = tid; e < 384; e += 256) {
        int v = e >> 4, f = e & 15;
        float dv = expf(-(float)(2 * f) * (9.210340371976184f / 32.0f));
        float a  = (float)v * (1.0f / 23.00000001f) * dv;
        ct[v][f] = cosf(a);
        st[v][f] = sinf(a);
    }
    __syncthreads();

    const int fi = lane >> 1;

#pragma unroll
    for (int t = 0; t < 2; t++) {
        __nv_bfloat16* dhi = t ? g_khi : g_qhi;
        __nv_bfloat16* dlo = t ? g_klo : g_qlo;
#pragma unroll
        for (int ps = 0; ps < 8; ps++) {
            int s = s0 + ps * 8 + wid;
            float v0 = 0.f, v1 = 0.f;
            bool valid = (s < S_LEN);
            if (valid) {
                const float* base = g_qkv + (size_t)t * HSTRIDE
                                  + ((size_t)bh * S_LEN + s) * DH;
                v0 = base[lane];
                v1 = base[lane + 32];
            }
            float p0 = __shfl_sync(full, v0, (lane + 31) & 31);
            float p1 = __shfl_sync(full, v1, (lane + 31) & 31);
            if (valid && s > 0) {
                int p  = s - 1;
                int px = p % 24, py = p / 24;
                v0 = v0 * ct[px][fi] + p0 * st[px][fi];
                v1 = v1 * ct[py][fi] + p1 * st[py][fi];
            }
            if (valid) {
                size_t off = ((size_t)bh * S_LEN + s) * DH;
                __nv_bfloat16 h0 = __float2bfloat16(v0);
                __nv_bfloat16 h1 = __float2bfloat16(v1);
                dhi[off + lane]      = h0;
                dhi[off + lane + 32] = h1;
                dlo[off + lane]      = __float2bfloat16(v0 - __bfloat162float(h0));
                dlo[off + lane + 32] = __float2bfloat16(v1 - __bfloat162float(h1));
            }
        }
    }

    __shared__ float vbuf[64][65];
#pragma unroll
    for (int it = 0; it < 16; it++) {
        int idx = tid + it * 256;
        int r = idx >> 6, c = idx & 63;
        float val = (s0 + r < S_LEN)
            ? g_qkv[2 * HSTRIDE + ((size_t)bh * S_LEN + s0 + r) * DH + c] : 0.f;
        vbuf[c][r] = val;
    }
    __syncthreads();
    {
        int d = tid >> 2, grp = tid & 3;
        __nv_bfloat16 hh[16], ll[16];
#pragma unroll
        for (int i = 0; i < 16; i++) {
            float f = vbuf[d][grp * 16 + i];
            hh[i] = __float2bfloat16(f);
            ll[i] = __float2bfloat16(f - __bfloat162float(hh[i]));
        }
        size_t dst = (size_t)bh * (DH * SPAD) + (size_t)d * SPAD + s0 + grp * 16;
        *(uint4*)(g_vthi + dst)     = *(uint4*)hh;
        *(uint4*)(g_vthi + dst + 8) = *(uint4*)(hh + 8);
        *(uint4*)(g_vtlo + dst)     = *(uint4*)ll;
        *(uint4*)(g_vtlo + dst + 8) = *(uint4*)(ll + 8);
    }
}

// ======================= HMMA flash attention (cp.async x2) =================
#define FLASH_SMEM 98304   // Q 32KB + 2 x (K hi/lo + V hi/lo = 32KB)

__global__ __launch_bounds__(256) void flash_mma()
{
    extern __shared__ char sm[];
    const uint32_t smem = smem_to_u32(sm);
    const uint32_t qh32 = smem, ql32 = smem + 16384;

    const int bh  = blockIdx.y;
    const int i0  = blockIdx.x * 128;
    const int tid = threadIdx.x;
    const int lane = tid & 31, wid = tid >> 5;

    // prefetch KV tile 0 via cp.async, then load Q synchronously (overlaps)
#define ISSUE_KV(t_)                                                           \
    {                                                                          \
        uint32_t kb_ = smem + 32768 + ((t_) & 1) * 32768;                      \
        int j0_ = (t_) * 64;                                                   \
        _Pragma("unroll")                                                      \
        for (int it = 0; it < 2; it++) {                                       \
            int idx = tid + it * 256;                                          \
            int r = idx >> 3, c = idx & 7;                                     \
            int sj = j0_ + r;                                                  \
            uint32_t szK = (sj < S_LEN) ? 16u : 0u;                            \
            size_t koff = ((size_t)bh * S_LEN + (sj < S_LEN ? sj : 0)) * DH + c * 8; \
            size_t voff = (size_t)bh * (DH * SPAD) + (size_t)r * SPAD + j0_ + c * 8; \
            uint32_t co = CH8(r, c);                                           \
            asm volatile("cp.async.cg.shared.global [%0], [%1], 16, %2;"       \
                :: "r"(kb_ + co), "l"(g_khi + koff), "r"(szK));                \
            asm volatile("cp.async.cg.shared.global [%0], [%1], 16, %2;"       \
                :: "r"(kb_ + 8192 + co), "l"(g_klo + koff), "r"(szK));         \
            asm volatile("cp.async.cg.shared.global [%0], [%1], 16;"           \
                :: "r"(kb_ + 16384 + co), "l"(g_vthi + voff));                 \
            asm volatile("cp.async.cg.shared.global [%0], [%1], 16;"           \
                :: "r"(kb_ + 24576 + co), "l"(g_vtlo + voff));                 \
        }                                                                      \
        asm volatile("cp.async.commit_group;");                                \
    }

    ISSUE_KV(0)

#pragma unroll
    for (int it = 0; it < 4; it++) {
        int idx = tid + it * 256;
        int r = idx >> 3, c = idx & 7;
        int s = i0 + r;
        uint4 vh = make_uint4(0u,0u,0u,0u), vl = vh;
        if (s < S_LEN) {
            size_t off = ((size_t)bh * S_LEN + s) * DH + c * 8;
            vh = *(const uint4*)(g_qhi + off);
            vl = *(const uint4*)(g_qlo + off);
        }
        *(uint4*)(sm + CH8(r, c)) = vh;
        *(uint4*)(sm + 16384 + CH8(r, c)) = vl;
    }
    __syncthreads();

    uint32_t qhf[4][4], qlf[4][4];
    {
        const int ar = wid * 16 + (lane & 7) + ((lane >> 3) & 1) * 8;
        const int ac = lane >> 4;
#pragma unroll
        for (int kt = 0; kt < 4; kt++) {
            LDSM4(qhf[kt], qh32 + CH8(ar, kt * 2 + ac));
            LDSM4(qlf[kt], ql32 + CH8(ar, kt * 2 + ac));
        }
    }

    float oacc[8][4] = {};
    float m0 = -1e30f, m1 = -1e30f, l0 = 0.f, l1 = 0.f;

    const int br = (lane & 7) + ((lane >> 4) << 3);
    const int bc = (lane >> 3) & 1;

    for (int t = 0; t < 10; t++) {
        const int j0 = t * 64;
        if (t + 1 < 10) {
            ISSUE_KV(t + 1)
            asm volatile("cp.async.wait_group 1;");
        } else {
            asm volatile("cp.async.wait_group 0;");
        }
        __syncthreads();

        const uint32_t kvb  = smem + 32768 + (t & 1) * 32768;
        const uint32_t kh32 = kvb,          kl32 = kvb + 8192;
        const uint32_t vh32 = kvb + 16384,  vl32 = kvb + 24576;

        float sacc[8][4] = {};
#pragma unroll
        for (int kt = 0; kt < 4; kt++) {
            uint32_t khf[4][4], klf[4][4];
#pragma unroll
            for (int g = 0; g < 4; g++) {
                uint32_t adr = CH8(g * 16 + br, kt * 2 + bc);
                LDSM4(khf[g], kh32 + adr);
                LDSM4(klf[g], kl32 + adr);
            }
#pragma unroll
            for (int g = 0; g < 4; g++)
#pragma unroll
                for (int hh = 0; hh < 2; hh++) {
                    const int j = g * 2 + hh;
                    MMA16816(sacc[j], qhf[kt], khf[g][hh*2], khf[g][hh*2+1]);
                    MMA16816(sacc[j], qhf[kt], klf[g][hh*2], klf[g][hh*2+1]);
                    MMA16816(sacc[j], qlf[kt], khf[g][hh*2], khf[g][hh*2+1]);
                }
        }

        float tm0 = -1e30f, tm1 = -1e30f;
#pragma unroll
        for (int nt = 0; nt < 8; nt++) {
            int jb = j0 + nt * 8 + (lane & 3) * 2;
            sacc[nt][0] = (jb     < S_LEN) ? sacc[nt][0] * 0.125f : -1e30f;
            sacc[nt][1] = (jb + 1 < S_LEN) ? sacc[nt][1] * 0.125f : -1e30f;
            sacc[nt][2] = (jb     < S_LEN) ? sacc[nt][2] * 0.125f : -1e30f;
            sacc[nt][3] = (jb + 1 < S_LEN) ? sacc[nt][3] * 0.125f : -1e30f;
            tm0 = fmaxf(tm0, fmaxf(sacc[nt][0], sacc[nt][1]));
            tm1 = fmaxf(tm1, fmaxf(sacc[nt][2], sacc[nt][3]));
        }
        tm0 = fmaxf(tm0, __shfl_xor_sync(0xffffffffu, tm0, 1));
        tm0 = fmaxf(tm0, __shfl_xor_sync(0xffffffffu, tm0, 2));
        tm1 = fmaxf(tm1, __shfl_xor_sync(0xffffffffu, tm1, 1));
        tm1 = fmaxf(tm1, __shfl_xor_sync(0xffffffffu, tm1, 2));
        float mn0 = fmaxf(m0, tm0), mn1 = fmaxf(m1, tm1);
        float f0 = __expf(m0 - mn0), f1 = __expf(m1 - mn1);
        m0 = mn0; m1 = mn1;

        float rs0 = 0.f, rs1 = 0.f;
#pragma unroll
        for (int nt = 0; nt < 8; nt++) {
            sacc[nt][0] = __expf(sacc[nt][0] - mn0);
            sacc[nt][1] = __expf(sacc[nt][1] - mn0);
            sacc[nt][2] = __expf(sacc[nt][2] - mn1);
            sacc[nt][3] = __expf(sacc[nt][3] - mn1);
            rs0 += sacc[nt][0] + sacc[nt][1];
            rs1 += sacc[nt][2] + sacc[nt][3];
        }
        rs0 += __shfl_xor_sync(0xffffffffu, rs0, 1);
        rs0 += __shfl_xor_sync(0xffffffffu, rs0, 2);
        rs1 += __shfl_xor_sync(0xffffffffu, rs1, 1);
        rs1 += __shfl_xor_sync(0xffffffffu, rs1, 2);
        l0 = l0 * f0 + rs0;
        l1 = l1 * f1 + rs1;

#pragma unroll
        for (int nt = 0; nt < 8; nt++) {
            oacc[nt][0] *= f0; oacc[nt][1] *= f0;
            oacc[nt][2] *= f1; oacc[nt][3] *= f1;
        }

        uint32_t pahi[4][4], palo[4][4];
#pragma unroll
        for (int kt = 0; kt < 4; kt++) {
            const int t0 = kt * 2, t1 = kt * 2 + 1;
            float v00 = sacc[t0][0], v01 = sacc[t0][1];
            float v02 = sacc[t0][2], v03 = sacc[t0][3];
            float v10 = sacc[t1][0], v11 = sacc[t1][1];
            float v12 = sacc[t1][2], v13 = sacc[t1][3];
            pahi[kt][0] = pk2bf(v00, v01);
            pahi[kt][1] = pk2bf(v02, v03);
            pahi[kt][2] = pk2bf(v10, v11);
            pahi[kt][3] = pk2bf(v12, v13);
            palo[kt][0] = pk2bf(v00 - __bfloat162float(__float2bfloat16(v00)),
                                v01 - __bfloat162float(__float2bfloat16(v01)));
            palo[kt][1] = pk2bf(v02 - __bfloat162float(__float2bfloat16(v02)),
                                v03 - __bfloat162float(__float2bfloat16(v03)));
            palo[kt][2] = pk2bf(v10 - __bfloat162float(__float2bfloat16(v10)),
                                v11 - __bfloat162float(__float2bfloat16(v11)));
            palo[kt][3] = pk2bf(v12 - __bfloat162float(__float2bfloat16(v12)),
                                v13 - __bfloat162float(__float2bfloat16(v13)));
        }

#pragma unroll
        for (int kt = 0; kt < 4; kt++) {
            uint32_t vhf[4][4], vlf[4][4];
#pragma unroll
            for (int g = 0; g < 4; g++) {
                uint32_t adr = CH8(g * 16 + br, kt * 2 + bc);
                LDSM4(vhf[g], vh32 + adr);
                LDSM4(vlf[g], vl32 + adr);
            }
#pragma unroll
            for (int g = 0; g < 4; g++)
#pragma unroll
                for (int hh = 0; hh < 2; hh++) {
                    const int j = g * 2 + hh;
                    MMA16816(oacc[j], pahi[kt], vhf[g][hh*2], vhf[g][hh*2+1]);
                    MMA16816(oacc[j], pahi[kt], vlf[g][hh*2], vlf[g][hh*2+1]);
                    MMA16816(oacc[j], palo[kt], vhf[g][hh*2], vhf[g][hh*2+1]);
                }
        }
        __syncthreads();   // separate compute(t) readers from ISSUE(t+2) writers
    }
#undef ISSUE_KV

    // epilogue: write ctx directly as bf16 hi/lo (input A of out-proj GEMM)
    const float inv0 = 1.f / l0, inv1 = 1.f / l1;
    const int b = bh / NH, h = bh % NH;
    const int r0 = i0 + wid * 16 + (lane >> 2);
    const int r1 = r0 + 8;
#pragma unroll
    for (int nt = 0; nt < 8; nt++) {
        int d = nt * 8 + (lane & 3) * 2;
        if (r0 < S_LEN) {
            float o0 = oacc[nt][0] * inv0, o1 = oacc[nt][1] * inv0;
            size_t off = ((size_t)b * S_LEN + r0) * E_DIM + h * DH + d;
            *(uint32_t*)&g_ahi[off] = pk2bf(o0, o1);
            *(uint32_t*)&g_alo[off] = pk2bf(o0 - __bfloat162float(__float2bfloat16(o0)),
                                            o1 - __bfloat162float(__float2bfloat16(o1)));
        }
        if (r1 < S_LEN) {
            float o2 = oacc[nt][2] * inv1, o3 = oacc[nt][3] * inv1;
            size_t off = ((size_t)b * S_LEN + r1) * E_DIM + h * DH + d;
            *(uint32_t*)&g_ahi[off] = pk2bf(o2, o3);
            *(uint32_t*)&g_alo[off] = pk2bf(o2 - __bfloat162float(__float2bfloat16(o2)),
                                            o3 - __bfloat162float(__float2bfloat16(o3)));
        }
    }
}

// ======================= launch =============================================
extern "C" void kernel_launch(void* const* d_in, const int* in_sizes, int n_in,
                              void* d_out, int out_size)
{
    (void)in_sizes; (void)n_in; (void)out_size;
    const float* x      = (const float*)d_in[0];
    const float* w_qkv  = (const float*)d_in[1];
    const float* w_proj = (const float*)d_in[2];
    float* out = (float*)d_out;

    void *ahi, *alo, *bhi, *blo;
    cudaGetSymbolAddress(&ahi, g_ahi);
    cudaGetSymbolAddress(&alo, g_alo);
    cudaGetSymbolAddress(&bhi, g_bhi);
    cudaGetSymbolAddress(&blo, g_blo);

    cudaFuncSetAttribute(mma_gemm<true>,  cudaFuncAttributeMaxDynamicSharedMemorySize, GEMM_SMEM);
    cudaFuncSetAttribute(mma_gemm<false>, cudaFuncAttributeMaxDynamicSharedMemorySize, GEMM_SMEM);
    cudaFuncSetAttribute(flash_mma, cudaFuncAttributeMaxDynamicSharedMemorySize, FLASH_SMEM);

    const int MT = (M_ROWS + 127) / 128;   // 145

    // 1) split x and w_qkv into bf16 hi/lo
    {
        int n4 = M_ROWS * E_DIM / 4;
        split_bf16<<<(n4 + 255) / 256, 256>>>((const float4*)x, (uint2*)ahi, (uint2*)alo, n4);
        int w4 = QKV_F * E_DIM / 4;
        split_bf16<<<(w4 + 255) / 256, 256>>>((const float4*)w_qkv, (uint2*)bhi, (uint2*)blo, w4);
    }

    // 2) QKV projection -> g_qkv [t][b][h][s][d]
    mma_gemm<true><<<dim3(QKV_F / 128, MT), 256, GEMM_SMEM>>>(nullptr);

    // 3) rope (table) + bf16 split of q,k + V transpose/split
    convert_rope_split<<<dim3(10, BH), 256>>>();

    // 4) HMMA flash attention -> ctx written as bf16 hi/lo into g_ahi/g_alo
    flash_mma<<<dim3(5, BH), 256, FLASH_SMEM>>>();

    // 5) split w_proj only (ctx hi/lo already produced by flash epilogue)
    {
        int w4 = E_DIM * E_DIM / 4;
        split_bf16<<<(w4 + 255) / 256, 256>>>((const float4*)w_proj, (uint2*)bhi, (uint2*)blo, w4);
    }

    // 6) output projection
    mma_gemm<false><<<dim3(E_DIM / 128, MT), 256, GEMM_SMEM>>>(out);
}

// round 11
// speedup vs baseline: 3.8375x; 1.1456x over previous
#include <cuda_runtime.h>
#include <cuda_bf16.h>
#include <math.h>
#include <stdint.h>

#define B_SZ   32
#define S_LEN  577
#define E_DIM  768
#define NH     12
#define DH     64
#define BH     (B_SZ * NH)         // 384
#define M_ROWS (B_SZ * S_LEN)      // 18464
#define QKV_F  (3 * E_DIM)         // 2304
#define SPAD   640
#define HSTRIDE ((size_t)B_SZ * NH * S_LEN * DH)

// Scratch (device globals; allocation-free per harness rules)
__device__ float g_qkv[(size_t)3 * B_SZ * NH * S_LEN * DH];  // [t][b][h][s][d]
__device__ __nv_bfloat16 g_ahi[(size_t)M_ROWS * E_DIM];
__device__ __nv_bfloat16 g_alo[(size_t)M_ROWS * E_DIM];
__device__ __nv_bfloat16 g_bhi[(size_t)QKV_F * E_DIM];
__device__ __nv_bfloat16 g_blo[(size_t)QKV_F * E_DIM];
// flash operands
__device__ __nv_bfloat16 g_qhi[(size_t)BH * S_LEN * DH];
__device__ __nv_bfloat16 g_qlo[(size_t)BH * S_LEN * DH];
__device__ __nv_bfloat16 g_khi[(size_t)BH * S_LEN * DH];
__device__ __nv_bfloat16 g_klo[(size_t)BH * S_LEN * DH];
__device__ __nv_bfloat16 g_vthi[(size_t)BH * DH * SPAD];     // [bh][d][s]
__device__ __nv_bfloat16 g_vtlo[(size_t)BH * DH * SPAD];

__device__ __forceinline__ uint32_t smem_to_u32(const void* p) {
    uint32_t a;
    asm("{ .reg .u64 t; cvta.to.shared.u64 t, %1; cvt.u32.u64 %0, t; }" : "=r"(a) : "l"(p));
    return a;
}

// ---- mma.sync helpers ----
#define LDSM4(r, addr)                                                         \
    asm volatile("ldmatrix.sync.aligned.m8n8.x4.shared.b16 {%0,%1,%2,%3}, [%4];" \
        : "=r"((r)[0]), "=r"((r)[1]), "=r"((r)[2]), "=r"((r)[3]) : "r"(addr))

#define MMA16816(d, a, b0, b1)                                                 \
    asm volatile("mma.sync.aligned.m16n8k16.row.col.f32.bf16.bf16.f32 "        \
        "{%0,%1,%2,%3}, {%4,%5,%6,%7}, {%8,%9}, {%0,%1,%2,%3};"                \
        : "+f"((d)[0]), "+f"((d)[1]), "+f"((d)[2]), "+f"((d)[3])               \
        : "r"((a)[0]), "r"((a)[1]), "r"((a)[2]), "r"((a)[3]), "r"(b0), "r"(b1))

// 16B-chunk swizzles
#define CHUNK_OFF(row, c) (((row) << 6) + ((((c) ^ (((row) >> 1) & 3))) << 4)) // [r][32bf16]
#define CH8(row, c)       (((row) << 7) + ((((c) ^ ((row) & 7))) << 4))        // [r][64bf16]

__device__ __forceinline__ uint32_t pk2bf(float f0, float f1) {
    __nv_bfloat162 h = __floats2bfloat162_rn(f0, f1);
    return *(uint32_t*)&h;
}

// ======================= bf16 hi/lo split (GEMM inputs) =====================
__global__ __launch_bounds__(256) void split_bf16(const float4* __restrict__ src,
                                                  uint2* __restrict__ hi,
                                                  uint2* __restrict__ lo, int n4)
{
    int i = blockIdx.x * blockDim.x + threadIdx.x;
    if (i >= n4) return;
    float4 v = src[i];
    __nv_bfloat16 h0 = __float2bfloat16(v.x), h1 = __float2bfloat16(v.y);
    __nv_bfloat16 h2 = __float2bfloat16(v.z), h3 = __float2bfloat16(v.w);
    __nv_bfloat16 l0 = __float2bfloat16(v.x - __bfloat162float(h0));
    __nv_bfloat16 l1 = __float2bfloat16(v.y - __bfloat162float(h1));
    __nv_bfloat16 l2 = __float2bfloat16(v.z - __bfloat162float(h2));
    __nv_bfloat16 l3 = __float2bfloat16(v.w - __bfloat162float(h3));
    uint2 hv, lv;
    hv.x = ((uint32_t)__bfloat16_as_ushort(h1) << 16) | __bfloat16_as_ushort(h0);
    hv.y = ((uint32_t)__bfloat16_as_ushort(h3) << 16) | __bfloat16_as_ushort(h2);
    lv.x = ((uint32_t)__bfloat16_as_ushort(l1) << 16) | __bfloat16_as_ushort(l0);
    lv.y = ((uint32_t)__bfloat16_as_ushort(l3) << 16) | __bfloat16_as_ushort(l2);
    hi[i] = hv;
    lo[i] = lv;
}

// ======================= HMMA GEMM (bf16x3, cp.async 2-stage, 2 CTA/SM) =====
#define GEMM_STAGE 32768
#define GEMM_SMEM  (2 * GEMM_STAGE)

template<bool QKV>
__global__ __launch_bounds__(256, 2) void mma_gemm(float* __restrict__ C)
{
    extern __shared__ char sm[];
    const int tid  = threadIdx.x;
    const int lane = tid & 31;
    const int wid  = tid >> 5;
    const int wm   = wid & 3;
    const int wn   = wid >> 2;
    const int row0 = blockIdx.y * 128;
    const int col0 = blockIdx.x * 128;
    const uint32_t smem = smem_to_u32(sm);

    const int lr = tid >> 2;
    const int lc = tid & 3;

    const int arow[2] = { wm * 32 + 0 * 16 + (lane & 7) + ((lane >> 3) & 1) * 8,
                          wm * 32 + 1 * 16 + (lane & 7) + ((lane >> 3) & 1) * 8 };
    const int achk = lane >> 4;
    const int brow[4] = { wn * 64 + 0 * 16 + (lane & 7) + (lane >> 4) * 8,
                          wn * 64 + 1 * 16 + (lane & 7) + (lane >> 4) * 8,
                          wn * 64 + 2 * 16 + (lane & 7) + (lane >> 4) * 8,
                          wn * 64 + 3 * 16 + (lane & 7) + (lane >> 4) * 8 };
    const int bchk = (lane >> 3) & 1;

#define ISSUE(s_)                                                              \
    {                                                                          \
        uint32_t sb_ = smem + ((s_) & 1) * GEMM_STAGE;                         \
        int k0_ = (s_) * 32;                                                   \
        _Pragma("unroll")                                                      \
        for (int p = 0; p < 2; p++) {                                          \
            int r = lr + p * 64;                                               \
            int rA = row0 + r;                                                 \
            uint32_t szA = (rA < M_ROWS) ? 16u : 0u;                           \
            size_t offA = (size_t)(rA < M_ROWS ? rA : 0) * E_DIM + k0_ + lc * 8; \
            size_t offB = (size_t)(col0 + r) * E_DIM + k0_ + lc * 8;           \
            uint32_t co = CHUNK_OFF(r, lc);                                    \
            asm volatile("cp.async.cg.shared.global [%0], [%1], 16, %2;"       \
                :: "r"(sb_ + co), "l"(g_ahi + offA), "r"(szA));                \
            asm volatile("cp.async.cg.shared.global [%0], [%1], 16, %2;"       \
                :: "r"(sb_ + 8192 + co), "l"(g_alo + offA), "r"(szA));         \
            asm volatile("cp.async.cg.shared.global [%0], [%1], 16;"           \
                :: "r"(sb_ + 16384 + co), "l"(g_bhi + offB));                  \
            asm volatile("cp.async.cg.shared.global [%0], [%1], 16;"           \
                :: "r"(sb_ + 24576 + co), "l"(g_blo + offB));                  \
        }                                                                      \
        asm volatile("cp.async.commit_group;");                                \
    }

    ISSUE(0)

    float acc[2][8][4] = {};

    for (int s = 0; s < 24; s++) {
        if (s + 1 < 24) {
            ISSUE(s + 1)
            asm volatile("cp.async.wait_group 1;");
        } else {
            asm volatile("cp.async.wait_group 0;");
        }
        __syncthreads();

        const uint32_t sb = smem + (s & 1) * GEMM_STAGE;
#pragma unroll
        for (int ks = 0; ks < 2; ks++) {
            uint32_t ah[2][4], al[2][4];
#pragma unroll
            for (int i = 0; i < 2; i++) {
                uint32_t adr = sb + CHUNK_OFF(arow[i], ks * 2 + achk);
                LDSM4(ah[i], adr);
                LDSM4(al[i], adr + 8192);
            }
            uint32_t bh[4][4], bl[4][4];
#pragma unroll
            for (int g = 0; g < 4; g++) {
                uint32_t adr = sb + 16384 + CHUNK_OFF(brow[g], ks * 2 + bchk);
                LDSM4(bh[g], adr);
                LDSM4(bl[g], adr + 8192);
            }
#pragma unroll
            for (int i = 0; i < 2; i++)
#pragma unroll
                for (int g = 0; g < 4; g++)
#pragma unroll
                    for (int hh = 0; hh < 2; hh++) {
                        const int j = g * 2 + hh;
                        MMA16816(acc[i][j], ah[i], bh[g][hh*2], bh[g][hh*2+1]);
                        MMA16816(acc[i][j], ah[i], bl[g][hh*2], bl[g][hh*2+1]);
                        MMA16816(acc[i][j], al[i], bh[g][hh*2], bh[g][hh*2+1]);
                    }
        }
        __syncthreads();   // compute(s) done before ISSUE(s+2) reuses this buffer
    }
#undef ISSUE

#pragma unroll
    for (int i = 0; i < 2; i++)
#pragma unroll
        for (int half = 0; half < 2; half++) {
            int m = row0 + wm * 32 + i * 16 + (lane >> 2) + half * 8;
            if (m >= M_ROWS) continue;
            int bb = 0, sIdx = 0;
            if (QKV) { bb = m / S_LEN; sIdx = m - bb * S_LEN; }
#pragma unroll
            for (int j = 0; j < 8; j++) {
                int n = col0 + wn * 64 + j * 8 + (lane & 3) * 2;
                float2 v = make_float2(acc[i][j][half*2], acc[i][j][half*2+1]);
                if (QKV) {
                    int t = n / E_DIM, r = n - t * E_DIM;
                    int h = r >> 6, d = r & 63;
                    *(float2*)&g_qkv[(size_t)t * HSTRIDE
                        + (((size_t)bb * NH + h) * S_LEN + sIdx) * DH + d] = v;
                } else {
                    *(float2*)&C[(size_t)m * E_DIM + n] = v;
                }
            }
        }
}

// ======================= convert: rope (table) + split + V transpose ========
__global__ __launch_bounds__(256) void convert_rope_split()
{
    const int bh    = blockIdx.y;
    const int chunk = blockIdx.x;
    const int s0    = chunk * 64;
    const int tid   = threadIdx.x;
    const int wid   = tid >> 5, lane = tid & 31;
    const unsigned full = 0xffffffffu;

    __shared__ float ct[24][16], st[24][16];
    for (int e = tid; e < 384; e += 256) {
        int v = e >> 4, f = e & 15;
        float dv = expf(-(float)(2 * f) * (9.210340371976184f / 32.0f));
        float a  = (float)v * (1.0f / 23.00000001f) * dv;
        ct[v][f] = cosf(a);
        st[v][f] = sinf(a);
    }
    __syncthreads();

    const int fi = lane >> 1;

#pragma unroll
    for (int t = 0; t < 2; t++) {
        __nv_bfloat16* dhi = t ? g_khi : g_qhi;
        __nv_bfloat16* dlo = t ? g_klo : g_qlo;
#pragma unroll
        for (int ps = 0; ps < 8; ps++) {
            int s = s0 + ps * 8 + wid;
            float v0 = 0.f, v1 = 0.f;
            bool valid = (s < S_LEN);
            if (valid) {
                const float* base = g_qkv + (size_t)t * HSTRIDE
                                  + ((size_t)bh * S_LEN + s) * DH;
                v0 = base[lane];
                v1 = base[lane + 32];
            }
            float p0 = __shfl_sync(full, v0, (lane + 31) & 31);
            float p1 = __shfl_sync(full, v1, (lane + 31) & 31);
            if (valid && s > 0) {
                int p  = s - 1;
                int px = p % 24, py = p / 24;
                v0 = v0 * ct[px][fi] + p0 * st[px][fi];
                v1 = v1 * ct[py][fi] + p1 * st[py][fi];
            }
            if (valid) {
                size_t off = ((size_t)bh * S_LEN + s) * DH;
                __nv_bfloat16 h0 = __float2bfloat16(v0);
                __nv_bfloat16 h1 = __float2bfloat16(v1);
                dhi[off + lane]      = h0;
                dhi[off + lane + 32] = h1;
                dlo[off + lane]      = __float2bfloat16(v0 - __bfloat162float(h0));
                dlo[off + lane + 32] = __float2bfloat16(v1 - __bfloat162float(h1));
            }
        }
    }

    __shared__ float vbuf[64][65];
#pragma unroll
    for (int it = 0; it < 16; it++) {
        int idx = tid + it * 256;
        int r = idx >> 6, c = idx & 63;
        float val = (s0 + r < S_LEN)
            ? g_qkv[2 * HSTRIDE + ((size_t)bh * S_LEN + s0 + r) * DH + c] : 0.f;
        vbuf[c][r] = val;
    }
    __syncthreads();
    {
        int d = tid >> 2, grp = tid & 3;
        __nv_bfloat16 hh[16], ll[16];
#pragma unroll
        for (int i = 0; i < 16; i++) {
            float f = vbuf[d][grp * 16 + i];
            hh[i] = __float2bfloat16(f);
            ll[i] = __float2bfloat16(f - __bfloat162float(hh[i]));
        }
        size_t dst = (size_t)bh * (DH * SPAD) + (size_t)d * SPAD + s0 + grp * 16;
        *(uint4*)(g_vthi + dst)     = *(uint4*)hh;
        *(uint4*)(g_vthi + dst + 8) = *(uint4*)(hh + 8);
        *(uint4*)(g_vtlo + dst)     = *(uint4*)ll;
        *(uint4*)(g_vtlo + dst + 8) = *(uint4*)(ll + 8);
    }
}

// ======================= HMMA flash attention (64KB, 2 CTA/SM) ==============
// Region A [0,32K): Q staging, then reused as KV buffer for odd tiles.
// Region B [32K,64K): KV buffer for even tiles.
#define FLASH_SMEM 65536

__global__ __launch_bounds__(256, 2) void flash_mma()
{
    extern __shared__ char sm[];
    const uint32_t smem = smem_to_u32(sm);

    const int bh  = blockIdx.y;
    const int i0  = blockIdx.x * 128;
    const int tid = threadIdx.x;
    const int lane = tid & 31, wid = tid >> 5;

    // KV buffer for tile t: even -> region B (32K), odd -> region A (0)
#define KVBASE(t_) (smem + (((t_) & 1) ? 0u : 32768u))

#define ISSUE_KV(t_)                                                           \
    {                                                                          \
        uint32_t kb_ = KVBASE(t_);                                             \
        int j0_ = (t_) * 64;                                                   \
        _Pragma("unroll")                                                      \
        for (int it = 0; it < 2; it++) {                                       \
            int idx = tid + it * 256;                                          \
            int r = idx >> 3, c = idx & 7;                                     \
            int sj = j0_ + r;                                                  \
            uint32_t szK = (sj < S_LEN) ? 16u : 0u;                            \
            size_t koff = ((size_t)bh * S_LEN + (sj < S_LEN ? sj : 0)) * DH + c * 8; \
            size_t voff = (size_t)bh * (DH * SPAD) + (size_t)r * SPAD + j0_ + c * 8; \
            uint32_t co = CH8(r, c);                                           \
            asm volatile("cp.async.cg.shared.global [%0], [%1], 16, %2;"       \
                :: "r"(kb_ + co), "l"(g_khi + koff), "r"(szK));                \
            asm volatile("cp.async.cg.shared.global [%0], [%1], 16, %2;"       \
                :: "r"(kb_ + 8192 + co), "l"(g_klo + koff), "r"(szK));         \
            asm volatile("cp.async.cg.shared.global [%0], [%1], 16;"           \
                :: "r"(kb_ + 16384 + co), "l"(g_vthi + voff));                 \
            asm volatile("cp.async.cg.shared.global [%0], [%1], 16;"           \
                :: "r"(kb_ + 24576 + co), "l"(g_vtlo + voff));                 \
        }                                                                      \
        asm volatile("cp.async.commit_group;");                                \
    }

    // tile 0 -> region B (doesn't clash with Q staging in region A)
    ISSUE_KV(0)

    // Q staging into region A: hi at 0 (16KB), lo at 16384
#pragma unroll
    for (int it = 0; it < 4; it++) {
        int idx = tid + it * 256;
        int r = idx >> 3, c = idx & 7;
        int s = i0 + r;
        uint4 vh = make_uint4(0u,0u,0u,0u), vl = vh;
        if (s < S_LEN) {
            size_t off = ((size_t)bh * S_LEN + s) * DH + c * 8;
            vh = *(const uint4*)(g_qhi + off);
            vl = *(const uint4*)(g_qlo + off);
        }
        *(uint4*)(sm + CH8(r, c)) = vh;
        *(uint4*)(sm + 16384 + CH8(r, c)) = vl;
    }
    __syncthreads();

    uint32_t qhf[4][4], qlf[4][4];
    {
        const int ar = wid * 16 + (lane & 7) + ((lane >> 3) & 1) * 8;
        const int ac = lane >> 4;
#pragma unroll
        for (int kt = 0; kt < 4; kt++) {
            LDSM4(qhf[kt], smem + CH8(ar, kt * 2 + ac));
            LDSM4(qlf[kt], smem + 16384 + CH8(ar, kt * 2 + ac));
        }
    }
    __syncthreads();   // all warps done reading Q region before KV(1) overwrites it

    ISSUE_KV(1)        // tile 1 -> region A (ex-Q)

    float oacc[8][4] = {};
    float m0 = -1e30f, m1 = -1e30f, l0 = 0.f, l1 = 0.f;

    const int br = (lane & 7) + ((lane >> 4) << 3);
    const int bc = (lane >> 3) & 1;

    for (int t = 0; t < 10; t++) {
        const int j0 = t * 64;
        if (t < 8) asm volatile("cp.async.wait_group 1;");
        else       asm volatile("cp.async.wait_group 0;");
        __syncthreads();

        const uint32_t kvb  = KVBASE(t);
        const uint32_t kh32 = kvb,          kl32 = kvb + 8192;
        const uint32_t vh32 = kvb + 16384,  vl32 = kvb + 24576;

        float sacc[8][4] = {};
#pragma unroll
        for (int kt = 0; kt < 4; kt++) {
            uint32_t khf[4][4], klf[4][4];
#pragma unroll
            for (int g = 0; g < 4; g++) {
                uint32_t adr = CH8(g * 16 + br, kt * 2 + bc);
                LDSM4(khf[g], kh32 + adr);
                LDSM4(klf[g], kl32 + adr);
            }
#pragma unroll
            for (int g = 0; g < 4; g++)
#pragma unroll
                for (int hh = 0; hh < 2; hh++) {
                    const int j = g * 2 + hh;
                    MMA16816(sacc[j], qhf[kt], khf[g][hh*2], khf[g][hh*2+1]);
                    MMA16816(sacc[j], qhf[kt], klf[g][hh*2], klf[g][hh*2+1]);
                    MMA16816(sacc[j], qlf[kt], khf[g][hh*2], khf[g][hh*2+1]);
                }
        }

        float tm0 = -1e30f, tm1 = -1e30f;
#pragma unroll
        for (int nt = 0; nt < 8; nt++) {
            int jb = j0 + nt * 8 + (lane & 3) * 2;
            sacc[nt][0] = (jb     < S_LEN) ? sacc[nt][0] * 0.125f : -1e30f;
            sacc[nt][1] = (jb + 1 < S_LEN) ? sacc[nt][1] * 0.125f : -1e30f;
            sacc[nt][2] = (jb     < S_LEN) ? sacc[nt][2] * 0.125f : -1e30f;
            sacc[nt][3] = (jb + 1 < S_LEN) ? sacc[nt][3] * 0.125f : -1e30f;
            tm0 = fmaxf(tm0, fmaxf(sacc[nt][0], sacc[nt][1]));
            tm1 = fmaxf(tm1, fmaxf(sacc[nt][2], sacc[nt][3]));
        }
        tm0 = fmaxf(tm0, __shfl_xor_sync(0xffffffffu, tm0, 1));
        tm0 = fmaxf(tm0, __shfl_xor_sync(0xffffffffu, tm0, 2));
        tm1 = fmaxf(tm1, __shfl_xor_sync(0xffffffffu, tm1, 1));
        tm1 = fmaxf(tm1, __shfl_xor_sync(0xffffffffu, tm1, 2));
        float mn0 = fmaxf(m0, tm0), mn1 = fmaxf(m1, tm1);
        float f0 = __expf(m0 - mn0), f1 = __expf(m1 - mn1);
        m0 = mn0; m1 = mn1;

        float rs0 = 0.f, rs1 = 0.f;
#pragma unroll
        for (int nt = 0; nt < 8; nt++) {
            sacc[nt][0] = __expf(sacc[nt][0] - mn0);
            sacc[nt][1] = __expf(sacc[nt][1] - mn0);
            sacc[nt][2] = __expf(sacc[nt][2] - mn1);
            sacc[nt][3] = __expf(sacc[nt][3] - mn1);
            rs0 += sacc[nt][0] + sacc[nt][1];
            rs1 += sacc[nt][2] + sacc[nt][3];
        }
        rs0 += __shfl_xor_sync(0xffffffffu, rs0, 1);
        rs0 += __shfl_xor_sync(0xffffffffu, rs0, 2);
        rs1 += __shfl_xor_sync(0xffffffffu, rs1, 1);
        rs1 += __shfl_xor_sync(0xffffffffu, rs1, 2);
        l0 = l0 * f0 + rs0;
        l1 = l1 * f1 + rs1;

#pragma unroll
        for (int nt = 0; nt < 8; nt++) {
            oacc[nt][0] *= f0; oacc[nt][1] *= f0;
            oacc[nt][2] *= f1; oacc[nt][3] *= f1;
        }

        uint32_t pahi[4][4], palo[4][4];
#pragma unroll
        for (int kt = 0; kt < 4; kt++) {
            const int t0 = kt * 2, t1 = kt * 2 + 1;
            float v00 = sacc[t0][0], v01 = sacc[t0][1];
            float v02 = sacc[t0][2], v03 = sacc[t0][3];
            float v10 = sacc[t1][0], v11 = sacc[t1][1];
            float v12 = sacc[t1][2], v13 = sacc[t1][3];
            pahi[kt][0] = pk2bf(v00, v01);
            pahi[kt][1] = pk2bf(v02, v03);
            pahi[kt][2] = pk2bf(v10, v11);
            pahi[kt][3] = pk2bf(v12, v13);
            palo[kt][0] = pk2bf(v00 - __bfloat162float(__float2bfloat16(v00)),
                                v01 - __bfloat162float(__float2bfloat16(v01)));
            palo[kt][1] = pk2bf(v02 - __bfloat162float(__float2bfloat16(v02)),
                                v03 - __bfloat162float(__float2bfloat16(v03)));
            palo[kt][2] = pk2bf(v10 - __bfloat162float(__float2bfloat16(v10)),
                                v11 - __bfloat162float(__float2bfloat16(v11)));
            palo[kt][3] = pk2bf(v12 - __bfloat162float(__float2bfloat16(v12)),
                                v13 - __bfloat162float(__float2bfloat16(v13)));
        }

#pragma unroll
        for (int kt = 0; kt < 4; kt++) {
            uint32_t vhf[4][4], vlf[4][4];
#pragma unroll
            for (int g = 0; g < 4; g++) {
                uint32_t adr = CH8(g * 16 + br, kt * 2 + bc);
                LDSM4(vhf[g], vh32 + adr);
                LDSM4(vlf[g], vl32 + adr);
            }
#pragma unroll
            for (int g = 0; g < 4; g++)
#pragma unroll
                for (int hh = 0; hh < 2; hh++) {
                    const int j = g * 2 + hh;
                    MMA16816(oacc[j], pahi[kt], vhf[g][hh*2], vhf[g][hh*2+1]);
                    MMA16816(oacc[j], pahi[kt], vlf[g][hh*2], vlf[g][hh*2+1]);
                    MMA16816(oacc[j], palo[kt], vhf[g][hh*2], vhf[g][hh*2+1]);
                }
        }
        __syncthreads();   // compute(t) done before ISSUE(t+2) reuses this buffer
        if (t + 2 < 10) ISSUE_KV(t + 2)
    }
#undef ISSUE_KV
#undef KVBASE

    // epilogue: write ctx directly as bf16 hi/lo (input A of out-proj GEMM)
    const float inv0 = 1.f / l0, inv1 = 1.f / l1;
    const int b = bh / NH, h = bh % NH;
    const int r0 = i0 + wid * 16 + (lane >> 2);
    const int r1 = r0 + 8;
#pragma unroll
    for (int nt = 0; nt < 8; nt++) {
        int d = nt * 8 + (lane & 3) * 2;
        if (r0 < S_LEN) {
            float o0 = oacc[nt][0] * inv0, o1 = oacc[nt][1] * inv0;
            size_t off = ((size_t)b * S_LEN + r0) * E_DIM + h * DH + d;
            *(uint32_t*)&g_ahi[off] = pk2bf(o0, o1);
            *(uint32_t*)&g_alo[off] = pk2bf(o0 - __bfloat162float(__float2bfloat16(o0)),
                                            o1 - __bfloat162float(__float2bfloat16(o1)));
        }
        if (r1 < S_LEN) {
            float o2 = oacc[nt][2] * inv1, o3 = oacc[nt][3] * inv1;
            size_t off = ((size_t)b * S_LEN + r1) * E_DIM + h * DH + d;
            *(uint32_t*)&g_ahi[off] = pk2bf(o2, o3);
            *(uint32_t*)&g_alo[off] = pk2bf(o2 - __bfloat162float(__float2bfloat16(o2)),
                                            o3 - __bfloat162float(__float2bfloat16(o3)));
        }
    }
}

// ======================= launch =============================================
extern "C" void kernel_launch(void* const* d_in, const int* in_sizes, int n_in,
                              void* d_out, int out_size)
{
    (void)in_sizes; (void)n_in; (void)out_size;
    const float* x      = (const float*)d_in[0];
    const float* w_qkv  = (const float*)d_in[1];
    const float* w_proj = (const float*)d_in[2];
    float* out = (float*)d_out;

    void *ahi, *alo, *bhi, *blo;
    cudaGetSymbolAddress(&ahi, g_ahi);
    cudaGetSymbolAddress(&alo, g_alo);
    cudaGetSymbolAddress(&bhi, g_bhi);
    cudaGetSymbolAddress(&blo, g_blo);

    cudaFuncSetAttribute(mma_gemm<true>,  cudaFuncAttributeMaxDynamicSharedMemorySize, GEMM_SMEM);
    cudaFuncSetAttribute(mma_gemm<false>, cudaFuncAttributeMaxDynamicSharedMemorySize, GEMM_SMEM);
    cudaFuncSetAttribute(flash_mma, cudaFuncAttributeMaxDynamicSharedMemorySize, FLASH_SMEM);

    const int MT = (M_ROWS + 127) / 128;   // 145

    // 1) split x and w_qkv into bf16 hi/lo
    {
        int n4 = M_ROWS * E_DIM / 4;
        split_bf16<<<(n4 + 255) / 256, 256>>>((const float4*)x, (uint2*)ahi, (uint2*)alo, n4);
        int w4 = QKV_F * E_DIM / 4;
        split_bf16<<<(w4 + 255) / 256, 256>>>((const float4*)w_qkv, (uint2*)bhi, (uint2*)blo, w4);
    }

    // 2) QKV projection -> g_qkv [t][b][h][s][d]
    mma_gemm<true><<<dim3(QKV_F / 128, MT), 256, GEMM_SMEM>>>(nullptr);

    // 3) rope (table) + bf16 split of q,k + V transpose/split
    convert_rope_split<<<dim3(10, BH), 256>>>();

    // 4) HMMA flash attention -> ctx written as bf16 hi/lo into g_ahi/g_alo
    flash_mma<<<dim3(5, BH), 256, FLASH_SMEM>>>();

    // 5) split w_proj only (ctx hi/lo already produced by flash epilogue)
    {
        int w4 = E_DIM * E_DIM / 4;
        split_bf16<<<(w4 + 255) / 256, 256>>>((const float4*)w_proj, (uint2*)bhi, (uint2*)blo, w4);
    }

    // 6) output projection
    mma_gemm<false><<<dim3(E_DIM / 128, MT), 256, GEMM_SMEM>>>(out);
}